// round 14
// baseline (speedup 1.0000x reference)
#include <cuda_runtime.h>
#include <math.h>

#define TY   50
#define BB   32
#define TXX  400
#define HH   512
#define CTXD 1024
#define DYD  512
#define G4   2048
#define VV   50000
#define VE   50050
#define HCAT 2048
#define NCHL 391      // k_logit blocks (391*128 = 50048 >= 50000)

// Output layout: flattened tree leaves of ((hs,cs), ss, atts, dists, Cs, ydecs)
#define OFF_HS   0LL
#define OFF_CSo  819200LL
#define OFF_SS   1638400LL
#define OFF_ATT  3276800LL
#define OFF_DIS  4915200LL
#define OFF_COV  5555200LL
#define OFF_YD   6195200LL

// ---------- scratch ----------
__device__ float g_pctx[(size_t)TXX*BB*CTXD];   // 52.4 MB
__device__ float g_h[BB*HH], g_c[BB*HH];
__device__ float g_h1[BB*HH], g_c1[BB*HH];
__device__ float g_acc[BB*TXX];
__device__ float g_hq[BB*CTXD];
__device__ float g_sc[BB*TXX];
__device__ float g_w[BB*TXX];
__device__ float g_att[BB*CTXD];
__device__ float g_ds[BB*HH];
__device__ float g_gg[BB];
__device__ float g_logit[(size_t)VV*BB];        // [v][b], 6.4 MB
__device__ float g_pm[NCHL*BB], g_ps[NCHL*BB];

// ---------- helpers ----------
__device__ __forceinline__ float sigf(float x){ return 1.f/(1.f+__expf(-x)); }
__device__ __forceinline__ float tanhfast(float x){
    x = fminf(15.f, fmaxf(-15.f, x));
    float e = __expf(2.f*x);
    return (e-1.f)/(e+1.f);
}
__device__ __forceinline__ float tanh_mufu(float x){
    float y;
    asm("tanh.approx.f32 %0, %1;" : "=f"(y) : "f"(x));
    return y;
}
__device__ __forceinline__ float warpSum(float v){
    #pragma unroll
    for(int o=16;o>0;o>>=1) v += __shfl_xor_sync(0xffffffffu, v, o);
    return v;
}
__device__ __forceinline__ float warpMax(float v){
    #pragma unroll
    for(int o=16;o>0;o>>=1) v = fmaxf(v, __shfl_xor_sync(0xffffffffu, v, o));
    return v;
}
// packed f32x2 FMA: d.lo += a.lo*b.lo ; d.hi += a.hi*b.hi  (native FFMA2 on sm_103a)
__device__ __forceinline__ void ffma2(unsigned long long &d, unsigned long long a,
                                      unsigned long long b){
    asm("fma.rn.f32x2 %0, %1, %2, %0;" : "+l"(d) : "l"(a), "l"(b));
}
__device__ __forceinline__ unsigned long long dup2(float w){
    unsigned long long r;
    asm("mov.b64 %0, {%1, %1};" : "=l"(r) : "f"(w));
    return r;
}
__device__ __forceinline__ unsigned long long pack2(float lo, float hi){
    unsigned long long r;
    asm("mov.b64 %0, {%1, %2};" : "=l"(r) : "f"(lo), "f"(hi));
    return r;
}
__device__ __forceinline__ void unpack2(unsigned long long p, float &lo, float &hi){
    asm("mov.b64 {%0, %1}, %2;" : "=f"(lo), "=f"(hi) : "l"(p));
}

// ---------- kernels ----------
__global__ void k_init(const float* __restrict__ h0, const float* __restrict__ c0,
                       const float* __restrict__ cov0){
    int i = blockIdx.x*256 + threadIdx.x;
    if(i < BB*HH){ g_h[i]=h0[i]; g_c[i]=c0[i]; }
    if(i < BB*TXX){ g_acc[i]=cov0[i]; }
}

// pctx[tb,d] = context[tb,:1024] . Wc[d,:1024] + b_att[d]
#define PCTB 8
__global__ void k_pctx(const float* __restrict__ ctx, const float* __restrict__ Wc,
                       const float* __restrict__ batt){
    __shared__ __align__(16) float xs[PCTB][CTXD];
    int tb0 = blockIdx.x*PCTB;
    int d   = blockIdx.y*256 + threadIdx.x;
    for(int i=threadIdx.x; i<PCTB*CTXD; i+=256){
        int r = i >> 10, k = i & 1023;
        xs[r][k] = ctx[(size_t)(tb0+r)*CTXD + k];
    }
    __syncthreads();
    const float4* w4 = (const float4*)(Wc + (size_t)d*CTXD);
    float acc[PCTB];
    #pragma unroll
    for(int r=0;r<PCTB;r++) acc[r]=0.f;
    #pragma unroll 2
    for(int k=0;k<CTXD/4;k++){
        float4 a = w4[k];
        #pragma unroll
        for(int r=0;r<PCTB;r++){
            float4 x = *(const float4*)&xs[r][k*4];
            acc[r] += a.x*x.x + a.y*x.y + a.z*x.z + a.w*x.w;
        }
    }
    float bb = batt[d];
    #pragma unroll
    for(int r=0;r<PCTB;r++)
        g_pctx[(size_t)(tb0+r)*CTXD + d] = acc[r] + bb;
}

// fused: gates (all 4 quadrants for this d-range) + LSTM cell1 + ss output
// grid (4, 32), 128 threads; thread d computes gates j = q*512+d for q=0..3
__global__ void k_gates_cell1(const float* __restrict__ x_t, const float* __restrict__ Wih,
                              const float* __restrict__ Whh, const float* __restrict__ bih,
                              const float* __restrict__ bhh, const float* __restrict__ ym_t,
                              float* __restrict__ ss_out){
    __shared__ __align__(16) float xs[DYD];
    __shared__ __align__(16) float hsh[HH];
    int b = blockIdx.y;
    int d = blockIdx.x*128 + threadIdx.x;
    for(int k=threadIdx.x;k<DYD;k+=128) xs[k]=x_t[(size_t)b*DYD+k];
    for(int k=threadIdx.x;k<HH;k+=128)  hsh[k]=g_h[b*HH+k];
    __syncthreads();
    const float4* x4=(const float4*)xs;
    const float4* h4=(const float4*)hsh;
    float g4[4];
    #pragma unroll
    for(int q=0;q<4;q++){
        int j = q*512 + d;
        const float4* wi=(const float4*)(Wih + (size_t)j*DYD);
        const float4* wh=(const float4*)(Whh + (size_t)j*HH);
        float acc = bih[j] + bhh[j];
        #pragma unroll 8
        for(int k=0;k<HH/4;k++){
            float4 a=wi[k], x=x4[k];
            acc += a.x*x.x + a.y*x.y + a.z*x.z + a.w*x.w;
            float4 c=wh[k], y=h4[k];
            acc += c.x*y.x + c.y*y.y + c.z*y.z + c.w*y.w;
        }
        g4[q]=acc;
    }
    int i = b*512 + d;
    float cp=g_c[i], hp=hsh[d], ym=ym_t[b];
    float c1 = sigf(g4[1])*cp + sigf(g4[0])*tanhfast(g4[2]);
    float h1 = sigf(g4[3])*tanhfast(c1);
    h1 = ym*h1 + (1.f-ym)*hp;
    c1 = ym*c1 + (1.f-ym)*cp;
    g_h1[i]=h1; g_c1[i]=c1;
    ss_out[b*1024 + d]       = h1;
    ss_out[b*1024 + 512 + d] = c1;
}

// hq[b,d] = [h1,c1](1024) . Wcomb[d,:1024]
__global__ void k_hq(const float* __restrict__ Wcomb){
    __shared__ __align__(16) float s[1024];
    int b = blockIdx.y;
    int d = blockIdx.x*256 + threadIdx.x;
    for(int k=threadIdx.x;k<512;k+=256){ s[k]=g_h1[b*512+k]; s[512+k]=g_c1[b*512+k]; }
    __syncthreads();
    const float4* w4=(const float4*)(Wcomb + (size_t)d*1024);
    const float4* s4=(const float4*)s;
    float acc=0.f;
    #pragma unroll 8
    for(int k=0;k<256;k++){
        float4 a=w4[k], x=s4[k];
        acc += a.x*x.x + a.y*x.y + a.z*x.z + a.w*x.w;
    }
    g_hq[b*1024+d]=acc;
}

// scores[tx,b] (warp per (tx,b) pair)
__global__ void k_scores(const float* __restrict__ xmask, const float* __restrict__ wcov,
                         const float* __restrict__ uatt){
    int p    = blockIdx.x*8 + (threadIdx.x >> 5);
    int lane = threadIdx.x & 31;
    int b = p & 31, tx = p >> 5;
    float a = g_acc[b*TXX + tx];
    const float4* p4 = (const float4*)(g_pctx + (size_t)p*CTXD);
    const float4* h4 = (const float4*)(g_hq + (size_t)b*CTXD);
    const float4* w4 = (const float4*)wcov;
    const float4* u4 = (const float4*)uatt;
    float acc = 0.f;
    #pragma unroll
    for(int it=0; it<8; it++){
        int k = it*32 + lane;
        float4 pp=p4[k], hh=h4[k], ww=w4[k], uu=u4[k];
        acc += tanh_mufu(pp.x+hh.x+a*ww.x)*uu.x;
        acc += tanh_mufu(pp.y+hh.y+a*ww.y)*uu.y;
        acc += tanh_mufu(pp.z+hh.z+a*ww.z)*uu.z;
        acc += tanh_mufu(pp.w+hh.w+a*ww.w)*uu.w;
    }
    acc = warpSum(acc);
    if(lane==0) g_sc[b*TXX + tx] = acc * xmask[tx*BB + b];
}

// fused: masked softmax over Tx + coverage update + atted;  grid 32, 1024 threads
__global__ void k_smax_atted(const float* __restrict__ xmask, const float* __restrict__ ctx,
                             float* __restrict__ dis_out, float* __restrict__ cov_out,
                             float* __restrict__ att_out){
    __shared__ float red[32];
    __shared__ float ws[TXX];
    int b = blockIdx.x, tid = threadIdx.x;   // 1024 threads
    int lane = tid & 31, wid = tid >> 5;
    float s = (tid < TXX) ? g_sc[b*TXX + tid] : -1e30f;
    float m = warpMax(s);
    if(lane==0) red[wid]=m;
    __syncthreads();
    if(tid<32){ float v=warpMax(red[tid]); if(tid==0) red[0]=v; }
    __syncthreads();
    m = red[0];
    float xm = (tid < TXX) ? xmask[tid*BB + b] : 0.f;
    float e  = (tid < TXX) ? __expf(s - m)*xm : 0.f;
    __syncthreads();
    float ss = warpSum(e);
    if(lane==0) red[wid]=ss;
    __syncthreads();
    if(tid<32){ float v=warpSum(red[tid]); if(tid==0) red[0]=v; }
    __syncthreads();
    float inv = 1.f/red[0];
    if(tid < TXX){
        float w = e*inv;
        ws[tid] = w;
        g_w[b*TXX + tid] = w;
        dis_out[b*TXX + tid] = w;
        float aa = g_acc[b*TXX + tid];
        cov_out[b*TXX + tid] = aa;
        g_acc[b*TXX + tid] = aa + w;
    }
    __syncthreads();
    // atted: c = tid (1024 channels), tx unrolled x8 for MLP
    int c = tid;
    const float* cb = ctx + (size_t)b*CTXD + c;
    const size_t str = (size_t)BB*CTXD;
    float a0=0.f,a1=0.f,a2=0.f,a3=0.f;
    #pragma unroll 1
    for(int t8=0;t8<TXX;t8+=8){
        a0 += ws[t8+0]*cb[(t8+0)*str];
        a1 += ws[t8+1]*cb[(t8+1)*str];
        a2 += ws[t8+2]*cb[(t8+2)*str];
        a3 += ws[t8+3]*cb[(t8+3)*str];
        a0 += ws[t8+4]*cb[(t8+4)*str];
        a1 += ws[t8+5]*cb[(t8+5)*str];
        a2 += ws[t8+6]*cb[(t8+6)*str];
        a3 += ws[t8+7]*cb[(t8+7)*str];
    }
    float acc = (a0+a1)+(a2+a3);
    g_att[b*CTXD+c]=acc;
    att_out[b*CTXD+c]=acc;
}

// fused: pre (all 4 quadrants) + LSTM cell2 + hs/cs outputs; grid (4,32), 128 thr
__global__ void k_pre_cell2(const float* __restrict__ Ux, const float* __restrict__ Wx,
                            const float* __restrict__ bx, const float* __restrict__ ym_t,
                            float* __restrict__ hs_out, float* __restrict__ cs_out){
    __shared__ __align__(16) float hsh[512];
    __shared__ __align__(16) float ash[1024];
    int b = blockIdx.y;
    int d = blockIdx.x*128 + threadIdx.x;
    for(int k=threadIdx.x;k<512;k+=128)  hsh[k]=g_h1[b*512+k];
    for(int k=threadIdx.x;k<1024;k+=128) ash[k]=g_att[b*CTXD+k];
    __syncthreads();
    const float4* h4=(const float4*)hsh;
    const float4* a4=(const float4*)ash;
    float g4[4];
    #pragma unroll
    for(int q=0;q<4;q++){
        int j = q*512 + d;
        const float4* u4=(const float4*)(Ux + (size_t)j*512);
        const float4* w4=(const float4*)(Wx + (size_t)j*1024);
        float acc = bx[j];
        #pragma unroll 8
        for(int k=0;k<128;k++){
            float4 a=u4[k], x=h4[k];
            acc += a.x*x.x + a.y*x.y + a.z*x.z + a.w*x.w;
        }
        #pragma unroll 8
        for(int k=0;k<256;k++){
            float4 c=w4[k], y=a4[k];
            acc += c.x*y.x + c.y*y.y + c.z*y.z + c.w*y.w;
        }
        g4[q]=acc;
    }
    int i = b*512 + d;
    float c1=g_c1[i], h1=hsh[d], ym=ym_t[b];
    // order i,f,o,c
    float c2 = sigf(g4[1])*c1 + sigf(g4[0])*tanhfast(g4[3]);
    float h2 = sigf(g4[2])*tanhfast(c2);
    c2 = ym*c2 + (1.f-ym)*c1;
    h2 = ym*h2 + (1.f-ym)*h1;
    g_h[i]=h2; g_c[i]=c2;
    hs_out[i]=h2; cs_out[i]=c2;
}

// ds[b,k] = tanh(hcat(2048).w_ds[k] + b_ds[k]);  block x==0 also computes g[b]
__global__ void k_ds(const float* __restrict__ x_t, const float* __restrict__ w_ds,
                     const float* __restrict__ b_ds, const float* __restrict__ vvec,
                     const float* __restrict__ bv){
    __shared__ __align__(16) float hc[HCAT];
    __shared__ float red[4];
    int b = blockIdx.y, tid = threadIdx.x;  // 128 threads, grid (4, 32)
    for(int i=tid;i<512;i+=128)  hc[i]       = g_h[b*512+i];
    for(int i=tid;i<1024;i+=128) hc[512+i]   = g_att[b*CTXD+i];
    for(int i=tid;i<512;i+=128)  hc[1536+i]  = x_t[(size_t)b*512+i];
    __syncthreads();
    int k = blockIdx.x*128 + tid;
    const float4* w4=(const float4*)(w_ds + (size_t)k*HCAT);
    const float4* h4=(const float4*)hc;
    float acc = b_ds[k];
    #pragma unroll 8
    for(int i=0;i<HCAT/4;i++){
        float4 a=w4[i], x=h4[i];
        acc += a.x*x.x + a.y*x.y + a.z*x.z + a.w*x.w;
    }
    g_ds[b*512+k] = tanhfast(acc);
    if(blockIdx.x==0){
        float pg = 0.f;
        for(int i=tid;i<HCAT;i+=128) pg += hc[i]*vvec[i];
        pg = warpSum(pg);
        if((tid&31)==0) red[tid>>5]=pg;
        __syncthreads();
        if(tid==0) g_gg[b] = sigf(red[0]+red[1]+red[2]+red[3] + bv[0]);
    }
}

// logit[v,b] via packed FFMA2 (2 batch lanes per instr); 1 v per thread, 391 blocks
// epilogue: per-block online-softmax partials
__global__ void __launch_bounds__(128) k_logit(const float* __restrict__ w_logit,
                                               const float* __restrict__ b_logit){
    __shared__ __align__(16) unsigned long long dsp[128][16]; // [k][b-pair], 16 KB
    __shared__ float red[128*33];                             // 16.9 KB
    __shared__ float msave[32];
    int tid = threadIdx.x;
    int v = blockIdx.x*128 + tid;
    bool val = v < VV;
    int vc = val ? v : VV-1;
    unsigned long long acc2[16];
    #pragma unroll
    for(int p=0;p<16;p++) acc2[p]=0ULL;
    for(int ch=0; ch<4; ch++){
        __syncthreads();
        // pack ds chunk: dsp[k][p] = (ds[2p][ch*128+k], ds[2p+1][ch*128+k])
        for(int i=tid; i<2048; i+=128){
            int k = i >> 4, p = i & 15;
            int kk = ch*128 + k;
            dsp[k][p] = pack2(g_ds[(2*p)*512 + kk], g_ds[(2*p+1)*512 + kk]);
        }
        __syncthreads();
        const float4* w4 = (const float4*)(w_logit + (size_t)vc*512 + ch*128);
        #pragma unroll 1
        for(int k4=0;k4<32;k4++){
            float4 a = w4[k4];
            #pragma unroll
            for(int kc=0;kc<4;kc++){
                float wv = (kc==0)?a.x:(kc==1)?a.y:(kc==2)?a.z:a.w;
                unsigned long long w2 = dup2(wv);
                const ulonglong2* row = (const ulonglong2*)&dsp[k4*4+kc][0];
                #pragma unroll
                for(int q=0;q<8;q++){
                    ulonglong2 pr = row[q];
                    ffma2(acc2[2*q],   w2, pr.x);
                    ffma2(acc2[2*q+1], w2, pr.y);
                }
            }
        }
    }
    // unpack, bias, store logits
    float accf[32];
    #pragma unroll
    for(int p=0;p<16;p++) unpack2(acc2[p], accf[2*p], accf[2*p+1]);
    if(val){
        float bl = b_logit[v];
        #pragma unroll
        for(int b=0;b<32;b++) accf[b]+=bl;
        float4* dst = (float4*)(g_logit + (size_t)v*32);
        #pragma unroll
        for(int q=0;q<8;q++){
            float4 o; o.x=accf[q*4]; o.y=accf[q*4+1]; o.z=accf[q*4+2]; o.w=accf[q*4+3];
            dst[q]=o;
        }
    }
    // per-block softmax partials over the 128 v of this block
    __syncthreads();
    #pragma unroll
    for(int b=0;b<32;b++) red[tid*33+b] = val ? accf[b] : -1e30f;
    __syncthreads();
    #pragma unroll
    for(int s=64;s>0;s>>=1){
        if(tid < s){
            #pragma unroll
            for(int b=0;b<32;b++)
                red[tid*33+b] = fmaxf(red[tid*33+b], red[(tid+s)*33+b]);
        }
        __syncthreads();
    }
    if(tid<32) msave[tid] = red[tid];
    __syncthreads();
    #pragma unroll
    for(int b=0;b<32;b++){
        float e = val ? __expf(accf[b]-msave[b]) : 0.f;
        red[tid*33+b] = e;
    }
    __syncthreads();
    #pragma unroll
    for(int s=64;s>0;s>>=1){
        if(tid < s){
            #pragma unroll
            for(int b=0;b<32;b++)
                red[tid*33+b] += red[(tid+s)*33+b];
        }
        __syncthreads();
    }
    if(tid<32){
        g_pm[blockIdx.x*32+tid] = msave[tid];
        g_ps[blockIdx.x*32+tid] = red[tid];
    }
}

// y_dec writer: final softmax reduce over NCHL partials + scale + coalesced transpose
__global__ void k_sm3(float* __restrict__ yd){
    __shared__ float tile[32][33];
    __shared__ float sM[32], sI[32], sG[32];
    __shared__ float pm[8][32], ps[8][32];
    int tid = threadIdx.x;           // 256 threads
    int b = tid & 31, grp = tid >> 5;
    float M = -1e30f, S = 0.f;
    for(int ch=grp; ch<NCHL; ch+=8){
        float m2 = g_pm[ch*32+b], s2 = g_ps[ch*32+b];
        float Mn = fmaxf(M, m2);
        S = S*__expf(M-Mn) + s2*__expf(m2-Mn);
        M = Mn;
    }
    pm[grp][b]=M; ps[grp][b]=S;
    __syncthreads();
    if(tid < 32){
        float Mf = pm[0][tid], Sf = ps[0][tid];
        #pragma unroll
        for(int k=1;k<8;k++){
            float m2=pm[k][tid], s2=ps[k][tid];
            float Mn=fmaxf(Mf,m2);
            Sf = Sf*__expf(Mf-Mn) + s2*__expf(m2-Mn);
            Mf = Mn;
        }
        sM[tid]=Mf; sI[tid]=1.f/Sf; sG[tid]=g_gg[tid];
    }
    __syncthreads();
    int vbase = blockIdx.x*256;
    for(int vt=0; vt<8; vt++){
        int v0t = vbase + vt*32;
        #pragma unroll
        for(int pass=0;pass<4;pass++){
            int vr = pass*8 + (tid>>5);
            int v  = v0t + vr;
            int bb = tid & 31;
            float val = 0.f;
            if(v < VV)
                val = sG[bb]*__expf(g_logit[(size_t)v*32+bb]-sM[bb])*sI[bb];
            tile[vr][bb] = val;
        }
        __syncthreads();
        #pragma unroll
        for(int pass=0;pass<4;pass++){
            int br = pass*8 + (tid>>5);
            int vl = tid & 31;
            int vw = v0t + vl;
            if(vw < VE) yd[(size_t)br*VE + vw] = tile[vl][br];
        }
        __syncthreads();
    }
}

// scatter-add (1-g)*watt at xid into y_dec
__global__ void k_scatter(const int* __restrict__ xid, float* __restrict__ yd){
    int i = blockIdx.x*256 + threadIdx.x;
    if(i >= BB*TXX) return;
    int tx = i >> 5, b = i & 31;
    int id = xid[tx*BB + b];
    if(id < 0 || id >= VE) return;
    float val = (1.f - g_gg[b]) * g_w[b*TXX + tx];
    atomicAdd(yd + (size_t)b*VE + id, val);
}

// ---------- host ----------
extern "C" void kernel_launch(void* const* d_in, const int* in_sizes, int n_in,
                              void* d_out, int out_size){
    const float* y_emb   = (const float*)d_in[0];
    const float* context = (const float*)d_in[1];
    const float* h0      = (const float*)d_in[2];
    const float* c0      = (const float*)d_in[3];
    const float* x_mask  = (const float*)d_in[4];
    const float* y_mask  = (const float*)d_in[5];
    const float* cov0    = (const float*)d_in[6];
    const float* Wih     = (const float*)d_in[7];
    const float* Whh     = (const float*)d_in[8];
    const float* bih     = (const float*)d_in[9];
    const float* bhh     = (const float*)d_in[10];
    const float* Wx      = (const float*)d_in[11];
    const float* Ux      = (const float*)d_in[12];
    const float* bx      = (const float*)d_in[13];
    const float* Wc      = (const float*)d_in[14];
    const float* b_att   = (const float*)d_in[15];
    const float* Wcomb   = (const float*)d_in[16];
    const float* Uatt    = (const float*)d_in[17];
    const float* Wcov    = (const float*)d_in[18];
    const float* w_ds    = (const float*)d_in[19];
    const float* b_ds    = (const float*)d_in[20];
    const float* w_logit = (const float*)d_in[21];
    const float* b_logit = (const float*)d_in[22];
    const float* vvec    = (const float*)d_in[23];
    const float* bv      = (const float*)d_in[24];
    const int*   xid     = (const int*)d_in[25];
    float* out = (float*)d_out;

    k_init<<<64,256>>>(h0, c0, cov0);
    k_pctx<<<dim3(TXX*BB/PCTB, CTXD/256), 256>>>(context, Wc, b_att);

    for(int t=0; t<TY; t++){
        const float* x_t = y_emb + (size_t)t*BB*DYD;
        const float* ym  = y_mask + (size_t)t*BB;

        k_gates_cell1<<<dim3(4,BB),128>>>(x_t, Wih, Whh, bih, bhh, ym,
                                          out + OFF_SS + (long long)t*BB*2*HH);
        k_hq<<<dim3(4,BB),256>>>(Wcomb);
        k_scores<<<1600,256>>>(x_mask, Wcov, Uatt);
        k_smax_atted<<<BB,1024>>>(x_mask, context,
                                  out + OFF_DIS + (long long)t*BB*TXX,
                                  out + OFF_COV + (long long)t*BB*TXX,
                                  out + OFF_ATT + (long long)t*BB*CTXD);
        k_pre_cell2<<<dim3(4,BB),128>>>(Ux, Wx, bx, ym,
                                        out + OFF_HS  + (long long)t*BB*HH,
                                        out + OFF_CSo + (long long)t*BB*HH);
        k_ds<<<dim3(4,BB),128>>>(x_t, w_ds, b_ds, vvec, bv);
        k_logit<<<NCHL,128>>>(w_logit, b_logit);
        k_sm3<<<196,256>>>(out + OFF_YD + (long long)t*BB*VE);
        k_scatter<<<50,256>>>(xid, out + OFF_YD + (long long)t*BB*VE);
    }
}

// round 15
// speedup vs baseline: 1.6448x; 1.6448x over previous
#include <cuda_runtime.h>
#include <math.h>

#define TY   50
#define BB   32
#define TXX  400
#define HH   512
#define CTXD 1024
#define DYD  512
#define G4   2048
#define VV   50000
#define VE   50050
#define HCAT 2048
#define NCH  196      // k_logit blocks = softmax chunks

// Output layout: flattened tree leaves of ((hs,cs), ss, atts, dists, Cs, ydecs)
#define OFF_HS   0LL
#define OFF_CSo  819200LL
#define OFF_SS   1638400LL
#define OFF_ATT  3276800LL
#define OFF_DIS  4915200LL
#define OFF_COV  5555200LL
#define OFF_YD   6195200LL

// ---------- scratch ----------
__device__ float g_pctx[(size_t)TXX*BB*CTXD];   // 52.4 MB
__device__ float g_h[BB*HH], g_c[BB*HH];
__device__ float g_h1[BB*HH], g_c1[BB*HH];
__device__ float g_acc[BB*TXX];
__device__ float g_gates[BB*G4];
__device__ float g_hq[BB*CTXD];
__device__ float g_sc[BB*TXX];
__device__ float g_w[BB*TXX];
__device__ float g_att[BB*CTXD];
__device__ float g_ds[BB*HH];
__device__ float g_gg[BB];
__device__ float g_logit[(size_t)VV*BB];        // [v][b], 6.4 MB
__device__ float g_pm[NCH*BB], g_ps[NCH*BB];

// ---------- helpers ----------
__device__ __forceinline__ float sigf(float x){ return 1.f/(1.f+__expf(-x)); }
__device__ __forceinline__ float tanhfast(float x){
    x = fminf(15.f, fmaxf(-15.f, x));
    float e = __expf(2.f*x);
    return (e-1.f)/(e+1.f);
}
__device__ __forceinline__ float tanh_mufu(float x){
    float y;
    asm("tanh.approx.f32 %0, %1;" : "=f"(y) : "f"(x));
    return y;
}
__device__ __forceinline__ float warpSum(float v){
    #pragma unroll
    for(int o=16;o>0;o>>=1) v += __shfl_xor_sync(0xffffffffu, v, o);
    return v;
}
__device__ __forceinline__ float warpMax(float v){
    #pragma unroll
    for(int o=16;o>0;o>>=1) v = fmaxf(v, __shfl_xor_sync(0xffffffffu, v, o));
    return v;
}
__device__ __forceinline__ float dot4(float4 a, float4 b){
    return a.x*b.x + a.y*b.y + a.z*b.z + a.w*b.w;
}

// ---------- kernels ----------
__global__ void k_init(const float* __restrict__ h0, const float* __restrict__ c0,
                       const float* __restrict__ cov0){
    int i = blockIdx.x*256 + threadIdx.x;
    if(i < BB*HH){ g_h[i]=h0[i]; g_c[i]=c0[i]; }
    if(i < BB*TXX){ g_acc[i]=cov0[i]; }
}

// pctx[tb,d] = context[tb,:1024] . Wc[d,:1024] + b_att[d]
#define PCTB 8
__global__ void k_pctx(const float* __restrict__ ctx, const float* __restrict__ Wc,
                       const float* __restrict__ batt){
    __shared__ __align__(16) float xs[PCTB][CTXD];
    int tb0 = blockIdx.x*PCTB;
    int d   = blockIdx.y*256 + threadIdx.x;
    for(int i=threadIdx.x; i<PCTB*CTXD; i+=256){
        int r = i >> 10, k = i & 1023;
        xs[r][k] = ctx[(size_t)(tb0+r)*CTXD + k];
    }
    __syncthreads();
    const float4* w4 = (const float4*)(Wc + (size_t)d*CTXD);
    float acc[PCTB];
    #pragma unroll
    for(int r=0;r<PCTB;r++) acc[r]=0.f;
    #pragma unroll 2
    for(int k=0;k<CTXD/4;k++){
        float4 a = w4[k];
        #pragma unroll
        for(int r=0;r<PCTB;r++)
            acc[r] += dot4(a, *(const float4*)&xs[r][k*4]);
    }
    float bb = batt[d];
    #pragma unroll
    for(int r=0;r<PCTB;r++)
        g_pctx[(size_t)(tb0+r)*CTXD + d] = acc[r] + bb;
}

// gates[b,j]: warp-per-j, coalesced weight reads, 8-b tile in smem
// grid (G4/8=256, BB/8=4), 256 threads (8 warps)
__global__ void k_gates(const float* __restrict__ x_t, const float* __restrict__ Wih,
                        const float* __restrict__ Whh, const float* __restrict__ bih,
                        const float* __restrict__ bhh){
    __shared__ __align__(16) float xs[8][DYD];
    __shared__ __align__(16) float hsm[8][HH];
    int tid = threadIdx.x, lane = tid & 31, w = tid >> 5;
    int b0 = blockIdx.y*8;
    int j  = blockIdx.x*8 + w;
    for(int i=tid;i<8*DYD;i+=256){ int r=i>>9, k=i&511; xs[r][k]=x_t[(size_t)(b0+r)*DYD+k]; }
    for(int i=tid;i<8*HH;i+=256){ int r=i>>9, k=i&511; hsm[r][k]=g_h[(b0+r)*HH+k]; }
    __syncthreads();
    const float4* wi=(const float4*)(Wih + (size_t)j*DYD);
    const float4* wh=(const float4*)(Whh + (size_t)j*HH);
    float acc[8];
    #pragma unroll
    for(int r=0;r<8;r++) acc[r]=0.f;
    #pragma unroll
    for(int it=0; it<4; it++){
        int k4 = it*32 + lane;
        float4 a = wi[k4];
        #pragma unroll
        for(int r=0;r<8;r++) acc[r] += dot4(a, *(const float4*)&xs[r][k4*4]);
        float4 c = wh[k4];
        #pragma unroll
        for(int r=0;r<8;r++) acc[r] += dot4(c, *(const float4*)&hsm[r][k4*4]);
    }
    float bias = bih[j] + bhh[j];
    #pragma unroll
    for(int r=0;r<8;r++){
        float s = warpSum(acc[r]);
        if(lane==0) g_gates[(b0+r)*G4 + j] = s + bias;
    }
}

// first LSTM cell (order i,f,g,o) + mask blend; writes ss output
__global__ void k_cell1(const float* __restrict__ ym_t, float* __restrict__ ss_out){
    int i = blockIdx.x*256 + threadIdx.x;   // 16384
    int b = i >> 9, d = i & 511;
    float gi=g_gates[b*G4+d],      gf=g_gates[b*G4+512+d];
    float gg=g_gates[b*G4+1024+d], go=g_gates[b*G4+1536+d];
    float cp=g_c[i], hp=g_h[i];
    float ym=ym_t[b];
    float c1 = sigf(gf)*cp + sigf(gi)*tanhfast(gg);
    float h1 = sigf(go)*tanhfast(c1);
    h1 = ym*h1 + (1.f-ym)*hp;
    c1 = ym*c1 + (1.f-ym)*cp;
    g_h1[i]=h1; g_c1[i]=c1;
    ss_out[b*1024 + d]       = h1;
    ss_out[b*1024 + 512 + d] = c1;
}

// hq[b,d]: warp-per-d, coalesced Wcomb reads, 8-b tile; grid (1024/8=128, 4)
__global__ void k_hq(const float* __restrict__ Wcomb){
    __shared__ __align__(16) float s[8][1024];
    int tid = threadIdx.x, lane = tid & 31, w = tid >> 5;
    int b0 = blockIdx.y*8;
    int d  = blockIdx.x*8 + w;
    for(int i=tid;i<8*512;i+=256){ int r=i>>9, k=i&511; s[r][k]=g_h1[(b0+r)*512+k]; }
    for(int i=tid;i<8*512;i+=256){ int r=i>>9, k=i&511; s[r][512+k]=g_c1[(b0+r)*512+k]; }
    __syncthreads();
    const float4* w4=(const float4*)(Wcomb + (size_t)d*1024);
    float acc[8];
    #pragma unroll
    for(int r=0;r<8;r++) acc[r]=0.f;
    #pragma unroll
    for(int it=0; it<8; it++){
        int k4 = it*32 + lane;
        float4 a = w4[k4];
        #pragma unroll
        for(int r=0;r<8;r++) acc[r] += dot4(a, *(const float4*)&s[r][k4*4]);
    }
    #pragma unroll
    for(int r=0;r<8;r++){
        float v = warpSum(acc[r]);
        if(lane==0) g_hq[(b0+r)*1024 + d] = v;
    }
}

// scores[tx,b] (warp per (tx,b) pair)
__global__ void k_scores(const float* __restrict__ xmask, const float* __restrict__ wcov,
                         const float* __restrict__ uatt){
    int p    = blockIdx.x*8 + (threadIdx.x >> 5);
    int lane = threadIdx.x & 31;
    int b = p & 31, tx = p >> 5;
    float a = g_acc[b*TXX + tx];
    const float4* p4 = (const float4*)(g_pctx + (size_t)p*CTXD);
    const float4* h4 = (const float4*)(g_hq + (size_t)b*CTXD);
    const float4* w4 = (const float4*)wcov;
    const float4* u4 = (const float4*)uatt;
    float acc = 0.f;
    #pragma unroll
    for(int it=0; it<8; it++){
        int k = it*32 + lane;
        float4 pp=p4[k], hh=h4[k], ww=w4[k], uu=u4[k];
        acc += tanh_mufu(pp.x+hh.x+a*ww.x)*uu.x;
        acc += tanh_mufu(pp.y+hh.y+a*ww.y)*uu.y;
        acc += tanh_mufu(pp.z+hh.z+a*ww.z)*uu.z;
        acc += tanh_mufu(pp.w+hh.w+a*ww.w)*uu.w;
    }
    acc = warpSum(acc);
    if(lane==0) g_sc[b*TXX + tx] = acc * xmask[tx*BB + b];
}

// masked softmax over Tx per b; writes dists + Cs, updates coverage
__global__ void k_smax_tx(const float* __restrict__ xmask, float* __restrict__ dis_out,
                          float* __restrict__ cov_out){
    __shared__ float red[32];
    int b = blockIdx.x, tid = threadIdx.x;  // 512 threads
    float s = (tid < TXX) ? g_sc[b*TXX + tid] : -1e30f;
    float m = warpMax(s);
    if((tid&31)==0) red[tid>>5]=m;
    __syncthreads();
    if(tid<32){ float v=(tid<16)?red[tid]:-1e30f; v=warpMax(v); if(tid==0) red[0]=v; }
    __syncthreads();
    m = red[0];
    float xm = (tid < TXX) ? xmask[tid*BB + b] : 0.f;
    float e  = (tid < TXX) ? __expf(s - m)*xm : 0.f;
    __syncthreads();
    float ss = warpSum(e);
    if((tid&31)==0) red[tid>>5]=ss;
    __syncthreads();
    if(tid<32){ float v=(tid<16)?red[tid]:0.f; v=warpSum(v); if(tid==0) red[0]=v; }
    __syncthreads();
    float inv = 1.f/red[0];
    if(tid < TXX){
        float w = e*inv;
        g_w[b*TXX + tid] = w;
        dis_out[b*TXX + tid] = w;
        float aa = g_acc[b*TXX + tid];
        cov_out[b*TXX + tid] = aa;
        g_acc[b*TXX + tid] = aa + w;
    }
}

// atted[b,c] = sum_tx w[b,tx] * context[tx,b,c]
__global__ void k_atted(const float* __restrict__ ctx, float* __restrict__ att_out){
    __shared__ float ws[TXX];
    int b = blockIdx.y;
    int c = blockIdx.x*256 + threadIdx.x;
    for(int k=threadIdx.x;k<TXX;k+=256) ws[k]=g_w[b*TXX+k];
    __syncthreads();
    const float* cb = ctx + (size_t)b*CTXD + c;
    float acc=0.f;
    #pragma unroll 4
    for(int tx=0;tx<TXX;tx++) acc += ws[tx]*cb[(size_t)tx*BB*CTXD];
    g_att[b*CTXD+c]=acc;
    att_out[b*CTXD+c]=acc;
}

// pre[b,j]: warp-per-j, coalesced Ux/Wx reads, 4-b tile; grid (256, 8)
__global__ void k_pre(const float* __restrict__ Ux, const float* __restrict__ Wx,
                      const float* __restrict__ bx){
    __shared__ __align__(16) float hsh[4][512];
    __shared__ __align__(16) float ash[4][1024];
    int tid = threadIdx.x, lane = tid & 31, w = tid >> 5;
    int b0 = blockIdx.y*4;
    int j  = blockIdx.x*8 + w;
    for(int i=tid;i<4*512;i+=256){ int r=i>>9, k=i&511; hsh[r][k]=g_h1[(b0+r)*512+k]; }
    for(int i=tid;i<4*1024;i+=256){ int r=i>>10, k=i&1023; ash[r][k]=g_att[(b0+r)*CTXD+k]; }
    __syncthreads();
    const float4* u4=(const float4*)(Ux + (size_t)j*512);
    const float4* w4=(const float4*)(Wx + (size_t)j*1024);
    float acc[4];
    #pragma unroll
    for(int r=0;r<4;r++) acc[r]=0.f;
    #pragma unroll
    for(int it=0; it<4; it++){
        int k4 = it*32 + lane;
        float4 a = u4[k4];
        #pragma unroll
        for(int r=0;r<4;r++) acc[r] += dot4(a, *(const float4*)&hsh[r][k4*4]);
    }
    #pragma unroll
    for(int it=0; it<8; it++){
        int k4 = it*32 + lane;
        float4 c = w4[k4];
        #pragma unroll
        for(int r=0;r<4;r++) acc[r] += dot4(c, *(const float4*)&ash[r][k4*4]);
    }
    float bias = bx[j];
    #pragma unroll
    for(int r=0;r<4;r++){
        float s = warpSum(acc[r]);
        if(lane==0) g_gates[(b0+r)*G4 + j] = s + bias;
    }
}

// second LSTM cell (order i,f,o,c!) + blend; writes hs/cs, updates state
__global__ void k_cell2(const float* __restrict__ ym_t, float* __restrict__ hs_out,
                        float* __restrict__ cs_out){
    int i = blockIdx.x*256 + threadIdx.x;
    int b = i >> 9, d = i & 511;
    float xi=g_gates[b*G4+d],      xf=g_gates[b*G4+512+d];
    float xo=g_gates[b*G4+1024+d], xc=g_gates[b*G4+1536+d];
    float c1=g_c1[i], h1=g_h1[i], ym=ym_t[b];
    float c2 = sigf(xf)*c1 + sigf(xi)*tanhfast(xc);
    float h2 = sigf(xo)*tanhfast(c2);
    c2 = ym*c2 + (1.f-ym)*c1;
    h2 = ym*h2 + (1.f-ym)*h1;
    g_h[i]=h2; g_c[i]=c2;
    hs_out[i]=h2; cs_out[i]=c2;
}

// ds[b,k]: warp-per-k, coalesced w_ds reads, 4-b tile; grid (64, 8)
// blockIdx.x==0 warps 0..3 also compute g[b] for their b
__global__ void k_ds(const float* __restrict__ x_t, const float* __restrict__ w_ds,
                     const float* __restrict__ b_ds, const float* __restrict__ vvec,
                     const float* __restrict__ bv){
    __shared__ __align__(16) float hc[4][HCAT];
    int tid = threadIdx.x, lane = tid & 31, w = tid >> 5;
    int b0 = blockIdx.y*4;
    int k  = blockIdx.x*8 + w;
    for(int i=tid;i<4*512;i+=256){ int r=i>>9, kk=i&511; hc[r][kk]=g_h[(b0+r)*512+kk]; }
    for(int i=tid;i<4*1024;i+=256){ int r=i>>10, kk=i&1023; hc[r][512+kk]=g_att[(b0+r)*CTXD+kk]; }
    for(int i=tid;i<4*512;i+=256){ int r=i>>9, kk=i&511; hc[r][1536+kk]=x_t[(size_t)(b0+r)*512+kk]; }
    __syncthreads();
    const float4* w4=(const float4*)(w_ds + (size_t)k*HCAT);
    float acc[4];
    #pragma unroll
    for(int r=0;r<4;r++) acc[r]=0.f;
    #pragma unroll
    for(int it=0; it<16; it++){
        int k4 = it*32 + lane;
        float4 a = w4[k4];
        #pragma unroll
        for(int r=0;r<4;r++) acc[r] += dot4(a, *(const float4*)&hc[r][k4*4]);
    }
    float bias = b_ds[k];
    #pragma unroll
    for(int r=0;r<4;r++){
        float s = warpSum(acc[r]);
        if(lane==0) g_ds[(b0+r)*512 + k] = tanhfast(s + bias);
    }
    if(blockIdx.x==0 && w < 4){
        // warp w computes g for b0+w
        const float4* v4 = (const float4*)vvec;
        float pg = 0.f;
        #pragma unroll
        for(int it=0; it<16; it++){
            int k4 = it*32 + lane;
            pg += dot4(v4[k4], *(const float4*)&hc[w][k4*4]);
        }
        pg = warpSum(pg);
        if(lane==0) g_gg[b0+w] = sigf(pg + bv[0]);
    }
}

// logit[v,b] = ds[b,:512].w_logit[v,:] + b_logit[v]; epilogue: softmax partials
__global__ void __launch_bounds__(128) k_logit(const float* __restrict__ w_logit,
                                               const float* __restrict__ b_logit){
    __shared__ __align__(16) float ds_s[32][128];
    __shared__ float red[128*33];
    __shared__ float msave[32];
    int tid = threadIdx.x;
    int v0 = blockIdx.x*256 + tid;
    int v1 = v0 + 128;
    int v0c = v0 < VV ? v0 : VV-1;
    int v1c = v1 < VV ? v1 : VV-1;
    bool val0 = v0 < VV, val1 = v1 < VV;
    float acc0[32], acc1[32];
    #pragma unroll
    for(int b=0;b<32;b++){ acc0[b]=0.f; acc1[b]=0.f; }
    for(int ch=0; ch<4; ch++){
        __syncthreads();
        for(int i=tid;i<4096;i+=128){
            int b=i>>7, kk=i&127;
            ds_s[b][kk]=g_ds[b*512 + ch*128 + kk];
        }
        __syncthreads();
        const float4* w0=(const float4*)(w_logit + (size_t)v0c*512 + ch*128);
        const float4* w1=(const float4*)(w_logit + (size_t)v1c*512 + ch*128);
        #pragma unroll 1
        for(int k4=0;k4<32;k4++){
            float4 a=w0[k4], c=w1[k4];
            #pragma unroll
            for(int b=0;b<32;b++){
                float4 dv = *(const float4*)&ds_s[b][k4*4];
                acc0[b] += dot4(dv, a);
                acc1[b] += dot4(dv, c);
            }
        }
    }
    if(val0){
        float bl = b_logit[v0];
        #pragma unroll
        for(int b=0;b<32;b++) acc0[b]+=bl;
        float4* dst = (float4*)(g_logit + (size_t)v0*32);
        #pragma unroll
        for(int q=0;q<8;q++){
            float4 o; o.x=acc0[q*4]; o.y=acc0[q*4+1]; o.z=acc0[q*4+2]; o.w=acc0[q*4+3];
            dst[q]=o;
        }
    }
    if(val1){
        float bl = b_logit[v1];
        #pragma unroll
        for(int b=0;b<32;b++) acc1[b]+=bl;
        float4* dst = (float4*)(g_logit + (size_t)v1*32);
        #pragma unroll
        for(int q=0;q<8;q++){
            float4 o; o.x=acc1[q*4]; o.y=acc1[q*4+1]; o.z=acc1[q*4+2]; o.w=acc1[q*4+3];
            dst[q]=o;
        }
    }
    __syncthreads();
    #pragma unroll
    for(int b=0;b<32;b++){
        float m = -1e30f;
        if(val0) m = acc0[b];
        if(val1) m = fmaxf(m, acc1[b]);
        red[tid*33+b] = m;
    }
    __syncthreads();
    #pragma unroll
    for(int s=64;s>0;s>>=1){
        if(tid < s){
            #pragma unroll
            for(int b=0;b<32;b++)
                red[tid*33+b] = fmaxf(red[tid*33+b], red[(tid+s)*33+b]);
        }
        __syncthreads();
    }
    if(tid<32) msave[tid] = red[tid];
    __syncthreads();
    #pragma unroll
    for(int b=0;b<32;b++){
        float M = msave[b];
        float e = 0.f;
        if(val0) e += __expf(acc0[b]-M);
        if(val1) e += __expf(acc1[b]-M);
        red[tid*33+b] = e;
    }
    __syncthreads();
    #pragma unroll
    for(int s=64;s>0;s>>=1){
        if(tid < s){
            #pragma unroll
            for(int b=0;b<32;b++)
                red[tid*33+b] += red[(tid+s)*33+b];
        }
        __syncthreads();
    }
    if(tid<32){
        g_pm[blockIdx.x*32+tid] = msave[tid];
        g_ps[blockIdx.x*32+tid] = red[tid];
    }
}

// y_dec writer: final softmax reduce + scale + coalesced transpose
__global__ void k_sm3(float* __restrict__ yd){
    __shared__ float tile[32][33];
    __shared__ float sM[32], sI[32], sG[32];
    __shared__ float pm[8][32], ps[8][32];
    int tid = threadIdx.x;           // 256 threads
    int b = tid & 31, grp = tid >> 5;
    float M = -1e30f, S = 0.f;
    for(int ch=grp; ch<NCH; ch+=8){
        float m2 = g_pm[ch*32+b], s2 = g_ps[ch*32+b];
        float Mn = fmaxf(M, m2);
        S = S*__expf(M-Mn) + s2*__expf(m2-Mn);
        M = Mn;
    }
    pm[grp][b]=M; ps[grp][b]=S;
    __syncthreads();
    if(tid < 32){
        float Mf = pm[0][tid], Sf = ps[0][tid];
        #pragma unroll
        for(int k=1;k<8;k++){
            float m2=pm[k][tid], s2=ps[k][tid];
            float Mn=fmaxf(Mf,m2);
            Sf = Sf*__expf(Mf-Mn) + s2*__expf(m2-Mn);
            Mf = Mn;
        }
        sM[tid]=Mf; sI[tid]=1.f/Sf; sG[tid]=g_gg[tid];
    }
    __syncthreads();
    int vbase = blockIdx.x*256;
    for(int vt=0; vt<8; vt++){
        int v0t = vbase + vt*32;
        #pragma unroll
        for(int pass=0;pass<4;pass++){
            int vr = pass*8 + (tid>>5);
            int v  = v0t + vr;
            int bb = tid & 31;
            float val = 0.f;
            if(v < VV)
                val = sG[bb]*__expf(g_logit[(size_t)v*32+bb]-sM[bb])*sI[bb];
            tile[vr][bb] = val;
        }
        __syncthreads();
        #pragma unroll
        for(int pass=0;pass<4;pass++){
            int br = pass*8 + (tid>>5);
            int vl = tid & 31;
            int vw = v0t + vl;
            if(vw < VE) yd[(size_t)br*VE + vw] = tile[vl][br];
        }
        __syncthreads();
    }
}

// scatter-add (1-g)*watt at xid into y_dec
__global__ void k_scatter(const int* __restrict__ xid, float* __restrict__ yd){
    int i = blockIdx.x*256 + threadIdx.x;
    if(i >= BB*TXX) return;
    int tx = i >> 5, b = i & 31;
    int id = xid[tx*BB + b];
    if(id < 0 || id >= VE) return;
    float val = (1.f - g_gg[b]) * g_w[b*TXX + tx];
    atomicAdd(yd + (size_t)b*VE + id, val);
}

// ---------- host ----------
extern "C" void kernel_launch(void* const* d_in, const int* in_sizes, int n_in,
                              void* d_out, int out_size){
    const float* y_emb   = (const float*)d_in[0];
    const float* context = (const float*)d_in[1];
    const float* h0      = (const float*)d_in[2];
    const float* c0      = (const float*)d_in[3];
    const float* x_mask  = (const float*)d_in[4];
    const float* y_mask  = (const float*)d_in[5];
    const float* cov0    = (const float*)d_in[6];
    const float* Wih     = (const float*)d_in[7];
    const float* Whh     = (const float*)d_in[8];
    const float* bih     = (const float*)d_in[9];
    const float* bhh     = (const float*)d_in[10];
    const float* Wx      = (const float*)d_in[11];
    const float* Ux      = (const float*)d_in[12];
    const float* bx      = (const float*)d_in[13];
    const float* Wc      = (const float*)d_in[14];
    const float* b_att   = (const float*)d_in[15];
    const float* Wcomb   = (const float*)d_in[16];
    const float* Uatt    = (const float*)d_in[17];
    const float* Wcov    = (const float*)d_in[18];
    const float* w_ds    = (const float*)d_in[19];
    const float* b_ds    = (const float*)d_in[20];
    const float* w_logit = (const float*)d_in[21];
    const float* b_logit = (const float*)d_in[22];
    const float* vvec    = (const float*)d_in[23];
    const float* bv      = (const float*)d_in[24];
    const int*   xid     = (const int*)d_in[25];
    float* out = (float*)d_out;

    k_init<<<64,256>>>(h0, c0, cov0);
    k_pctx<<<dim3(TXX*BB/PCTB, CTXD/256), 256>>>(context, Wc, b_att);

    for(int t=0; t<TY; t++){
        const float* x_t = y_emb + (size_t)t*BB*DYD;
        const float* ym  = y_mask + (size_t)t*BB;

        k_gates<<<dim3(G4/8, BB/8), 256>>>(x_t, Wih, Whh, bih, bhh);
        k_cell1<<<64,256>>>(ym, out + OFF_SS + (long long)t*BB*2*HH);
        k_hq<<<dim3(CTXD/8, BB/8), 256>>>(Wcomb);
        k_scores<<<1600,256>>>(x_mask, Wcov, Uatt);
        k_smax_tx<<<BB,512>>>(x_mask,
                              out + OFF_DIS + (long long)t*BB*TXX,
                              out + OFF_COV + (long long)t*BB*TXX);
        k_atted<<<dim3(4,BB),256>>>(context, out + OFF_ATT + (long long)t*BB*CTXD);
        k_pre<<<dim3(G4/8, BB/4), 256>>>(Ux, Wx, bx);
        k_cell2<<<64,256>>>(ym,
                            out + OFF_HS  + (long long)t*BB*HH,
                            out + OFF_CSo + (long long)t*BB*HH);
        k_ds<<<dim3(HH/8, BB/4), 256>>>(x_t, w_ds, b_ds, vvec, bv);
        k_logit<<<NCH,128>>>(w_logit, b_logit);
        k_sm3<<<NCH,256>>>(out + OFF_YD + (long long)t*BB*VE);
        k_scatter<<<50,256>>>(xid, out + OFF_YD + (long long)t*BB*VE);
    }
}

// round 16
// speedup vs baseline: 2.6501x; 1.6112x over previous
#include <cuda_runtime.h>
#include <math.h>

#define TY   50
#define BB   32
#define TXX  400
#define HH   512
#define CTXD 1024
#define DYD  512
#define G4   2048
#define VV   50000
#define VE   50050
#define HCAT 2048
#define NCH  196      // k_logit blocks = softmax chunks

// Output layout: flattened tree leaves of ((hs,cs), ss, atts, dists, Cs, ydecs)
#define OFF_HS   0LL
#define OFF_CSo  819200LL
#define OFF_SS   1638400LL
#define OFF_ATT  3276800LL
#define OFF_DIS  4915200LL
#define OFF_COV  5555200LL
#define OFF_YD   6195200LL

// ---------- scratch ----------
__device__ float g_pctx[(size_t)TXX*BB*CTXD];   // 52.4 MB
__device__ float g_h[BB*HH], g_c[BB*HH];
__device__ float g_h1[BB*HH], g_c1[BB*HH];
__device__ float g_acc[BB*TXX];
__device__ float g_hq[BB*CTXD];
__device__ float g_sc[BB*TXX];
__device__ float g_w[BB*TXX];
__device__ float g_att[BB*CTXD];
__device__ float g_ds[BB*HH];
__device__ float g_gg[BB];
__device__ float g_logit[(size_t)VV*BB];        // [v][b], 6.4 MB
__device__ float g_pm[NCH*BB], g_ps[NCH*BB];

// ---------- helpers ----------
__device__ __forceinline__ float sigf(float x){ return 1.f/(1.f+__expf(-x)); }
__device__ __forceinline__ float tanhfast(float x){
    x = fminf(15.f, fmaxf(-15.f, x));
    float e = __expf(2.f*x);
    return (e-1.f)/(e+1.f);
}
__device__ __forceinline__ float tanh_mufu(float x){
    float y;
    asm("tanh.approx.f32 %0, %1;" : "=f"(y) : "f"(x));
    return y;
}
__device__ __forceinline__ float warpSum(float v){
    #pragma unroll
    for(int o=16;o>0;o>>=1) v += __shfl_xor_sync(0xffffffffu, v, o);
    return v;
}
__device__ __forceinline__ float warpMax(float v){
    #pragma unroll
    for(int o=16;o>0;o>>=1) v = fmaxf(v, __shfl_xor_sync(0xffffffffu, v, o));
    return v;
}
__device__ __forceinline__ float dot4(float4 a, float4 b){
    return a.x*b.x + a.y*b.y + a.z*b.z + a.w*b.w;
}
// packed f32x2 FMA: d += a*b elementwise on 2 packed floats (exact fp32)
__device__ __forceinline__ void ffma2(unsigned long long &d, unsigned long long a,
                                      unsigned long long b){
    asm("fma.rn.f32x2 %0, %1, %2, %0;" : "+l"(d) : "l"(a), "l"(b));
}
__device__ __forceinline__ unsigned long long dup2(float w){
    unsigned long long r;
    asm("mov.b64 %0, {%1, %1};" : "=l"(r) : "f"(w));
    return r;
}
__device__ __forceinline__ unsigned long long pack2(float lo, float hi){
    unsigned long long r;
    asm("mov.b64 %0, {%1, %2};" : "=l"(r) : "f"(lo), "f"(hi));
    return r;
}
__device__ __forceinline__ void unpack2(unsigned long long p, float &lo, float &hi){
    asm("mov.b64 {%0, %1}, %2;" : "=f"(lo), "=f"(hi) : "l"(p));
}

// ---------- kernels ----------
__global__ void k_init(const float* __restrict__ h0, const float* __restrict__ c0,
                       const float* __restrict__ cov0){
    int i = blockIdx.x*256 + threadIdx.x;
    if(i < BB*HH){ g_h[i]=h0[i]; g_c[i]=c0[i]; }
    if(i < BB*TXX){ g_acc[i]=cov0[i]; }
}

// pctx[tb,d] = context[tb,:1024] . Wc[d,:1024] + b_att[d]
#define PCTB 8
__global__ void k_pctx(const float* __restrict__ ctx, const float* __restrict__ Wc,
                       const float* __restrict__ batt){
    __shared__ __align__(16) float xs[PCTB][CTXD];
    int tb0 = blockIdx.x*PCTB;
    int d   = blockIdx.y*256 + threadIdx.x;
    for(int i=threadIdx.x; i<PCTB*CTXD; i+=256){
        int r = i >> 10, k = i & 1023;
        xs[r][k] = ctx[(size_t)(tb0+r)*CTXD + k];
    }
    __syncthreads();
    const float4* w4 = (const float4*)(Wc + (size_t)d*CTXD);
    float acc[PCTB];
    #pragma unroll
    for(int r=0;r<PCTB;r++) acc[r]=0.f;
    #pragma unroll 2
    for(int k=0;k<CTXD/4;k++){
        float4 a = w4[k];
        #pragma unroll
        for(int r=0;r<PCTB;r++)
            acc[r] += dot4(a, *(const float4*)&xs[r][k*4]);
    }
    float bb = batt[d];
    #pragma unroll
    for(int r=0;r<PCTB;r++)
        g_pctx[(size_t)(tb0+r)*CTXD + d] = acc[r] + bb;
}

// fused gates+cell1: block = 2 d-values x 4 quadrants x 8 b; warp-per-weight-row
// grid (HH/2=256, BB/8=4), 256 threads
__global__ void k_gates_cell1(const float* __restrict__ x_t, const float* __restrict__ Wih,
                              const float* __restrict__ Whh, const float* __restrict__ bih,
                              const float* __restrict__ bhh, const float* __restrict__ ym_t,
                              float* __restrict__ ss_out){
    __shared__ __align__(16) float xs[8][DYD];
    __shared__ __align__(16) float hsm[8][HH];
    __shared__ float gsm[4][2][8];   // [quadrant][d-offset][b-row]
    int tid = threadIdx.x, lane = tid & 31, w = tid >> 5;
    int b0 = blockIdx.y*8;
    int d0 = blockIdx.x*2;
    for(int i=tid;i<8*DYD;i+=256){ int r=i>>9, k=i&511; xs[r][k]=x_t[(size_t)(b0+r)*DYD+k]; }
    for(int i=tid;i<8*HH;i+=256){ int r=i>>9, k=i&511; hsm[r][k]=g_h[(b0+r)*HH+k]; }
    __syncthreads();
    int q = w >> 1, dd = w & 1;
    int j = q*512 + d0 + dd;
    const float4* wi=(const float4*)(Wih + (size_t)j*DYD);
    const float4* wh=(const float4*)(Whh + (size_t)j*HH);
    float acc[8];
    #pragma unroll
    for(int r=0;r<8;r++) acc[r]=0.f;
    #pragma unroll
    for(int it=0; it<4; it++){
        int k4 = it*32 + lane;
        float4 a = wi[k4];
        #pragma unroll
        for(int r=0;r<8;r++) acc[r] += dot4(a, *(const float4*)&xs[r][k4*4]);
        float4 c = wh[k4];
        #pragma unroll
        for(int r=0;r<8;r++) acc[r] += dot4(c, *(const float4*)&hsm[r][k4*4]);
    }
    float bias = bih[j] + bhh[j];
    #pragma unroll
    for(int r=0;r<8;r++){
        float s = warpSum(acc[r]);
        if(lane==0) gsm[q][dd][r] = s + bias;
    }
    __syncthreads();
    if(tid < 16){
        int r = tid & 7, d2 = tid >> 3;
        int b = b0 + r, d = d0 + d2;
        int i = b*512 + d;
        float gi=gsm[0][d2][r], gf=gsm[1][d2][r], gg=gsm[2][d2][r], go=gsm[3][d2][r];
        float cp=g_c[i], hp=hsm[r][d], ym=ym_t[b];
        float c1 = sigf(gf)*cp + sigf(gi)*tanhfast(gg);
        float h1 = sigf(go)*tanhfast(c1);
        h1 = ym*h1 + (1.f-ym)*hp;
        c1 = ym*c1 + (1.f-ym)*cp;
        g_h1[i]=h1; g_c1[i]=c1;
        ss_out[b*1024 + d]       = h1;
        ss_out[b*1024 + 512 + d] = c1;
    }
}

// hq[b,d]: warp-per-d, coalesced Wcomb reads, 8-b tile; grid (128, 4)
__global__ void k_hq(const float* __restrict__ Wcomb){
    __shared__ __align__(16) float s[8][1024];
    int tid = threadIdx.x, lane = tid & 31, w = tid >> 5;
    int b0 = blockIdx.y*8;
    int d  = blockIdx.x*8 + w;
    for(int i=tid;i<8*512;i+=256){ int r=i>>9, k=i&511; s[r][k]=g_h1[(b0+r)*512+k]; }
    for(int i=tid;i<8*512;i+=256){ int r=i>>9, k=i&511; s[r][512+k]=g_c1[(b0+r)*512+k]; }
    __syncthreads();
    const float4* w4=(const float4*)(Wcomb + (size_t)d*1024);
    float acc[8];
    #pragma unroll
    for(int r=0;r<8;r++) acc[r]=0.f;
    #pragma unroll
    for(int it=0; it<8; it++){
        int k4 = it*32 + lane;
        float4 a = w4[k4];
        #pragma unroll
        for(int r=0;r<8;r++) acc[r] += dot4(a, *(const float4*)&s[r][k4*4]);
    }
    #pragma unroll
    for(int r=0;r<8;r++){
        float v = warpSum(acc[r]);
        if(lane==0) g_hq[(b0+r)*1024 + d] = v;
    }
}

// scores[tx,b] (warp per (tx,b) pair)
__global__ void k_scores(const float* __restrict__ xmask, const float* __restrict__ wcov,
                         const float* __restrict__ uatt){
    int p    = blockIdx.x*8 + (threadIdx.x >> 5);
    int lane = threadIdx.x & 31;
    int b = p & 31, tx = p >> 5;
    float a = g_acc[b*TXX + tx];
    const float4* p4 = (const float4*)(g_pctx + (size_t)p*CTXD);
    const float4* h4 = (const float4*)(g_hq + (size_t)b*CTXD);
    const float4* w4 = (const float4*)wcov;
    const float4* u4 = (const float4*)uatt;
    float acc = 0.f;
    #pragma unroll
    for(int it=0; it<8; it++){
        int k = it*32 + lane;
        float4 pp=p4[k], hh=h4[k], ww=w4[k], uu=u4[k];
        acc += tanh_mufu(pp.x+hh.x+a*ww.x)*uu.x;
        acc += tanh_mufu(pp.y+hh.y+a*ww.y)*uu.y;
        acc += tanh_mufu(pp.z+hh.z+a*ww.z)*uu.z;
        acc += tanh_mufu(pp.w+hh.w+a*ww.w)*uu.w;
    }
    acc = warpSum(acc);
    if(lane==0) g_sc[b*TXX + tx] = acc * xmask[tx*BB + b];
}

// masked softmax over Tx per b; writes dists + Cs, updates coverage
__global__ void k_smax_tx(const float* __restrict__ xmask, float* __restrict__ dis_out,
                          float* __restrict__ cov_out){
    __shared__ float red[32];
    int b = blockIdx.x, tid = threadIdx.x;  // 512 threads
    float s = (tid < TXX) ? g_sc[b*TXX + tid] : -1e30f;
    float m = warpMax(s);
    if((tid&31)==0) red[tid>>5]=m;
    __syncthreads();
    if(tid<32){ float v=(tid<16)?red[tid]:-1e30f; v=warpMax(v); if(tid==0) red[0]=v; }
    __syncthreads();
    m = red[0];
    float xm = (tid < TXX) ? xmask[tid*BB + b] : 0.f;
    float e  = (tid < TXX) ? __expf(s - m)*xm : 0.f;
    __syncthreads();
    float ss = warpSum(e);
    if((tid&31)==0) red[tid>>5]=ss;
    __syncthreads();
    if(tid<32){ float v=(tid<16)?red[tid]:0.f; v=warpSum(v); if(tid==0) red[0]=v; }
    __syncthreads();
    float inv = 1.f/red[0];
    if(tid < TXX){
        float w = e*inv;
        g_w[b*TXX + tid] = w;
        dis_out[b*TXX + tid] = w;
        float aa = g_acc[b*TXX + tid];
        cov_out[b*TXX + tid] = aa;
        g_acc[b*TXX + tid] = aa + w;
    }
}

// atted[b,c] = sum_tx w[b,tx] * context[tx,b,c];  8-deep MLP unroll
__global__ void k_atted(const float* __restrict__ ctx, float* __restrict__ att_out){
    __shared__ float ws[TXX];
    int b = blockIdx.y;
    int c = blockIdx.x*256 + threadIdx.x;
    for(int k=threadIdx.x;k<TXX;k+=256) ws[k]=g_w[b*TXX+k];
    __syncthreads();
    const float* cb = ctx + (size_t)b*CTXD + c;
    const size_t str = (size_t)BB*CTXD;
    float a0=0.f,a1=0.f,a2=0.f,a3=0.f;
    #pragma unroll 2
    for(int t8=0;t8<TXX;t8+=8){
        float v0=cb[(t8+0)*str], v1=cb[(t8+1)*str], v2=cb[(t8+2)*str], v3=cb[(t8+3)*str];
        float v4=cb[(t8+4)*str], v5=cb[(t8+5)*str], v6=cb[(t8+6)*str], v7=cb[(t8+7)*str];
        a0 += ws[t8+0]*v0; a1 += ws[t8+1]*v1;
        a2 += ws[t8+2]*v2; a3 += ws[t8+3]*v3;
        a0 += ws[t8+4]*v4; a1 += ws[t8+5]*v5;
        a2 += ws[t8+6]*v6; a3 += ws[t8+7]*v7;
    }
    float acc = (a0+a1)+(a2+a3);
    g_att[b*CTXD+c]=acc;
    att_out[b*CTXD+c]=acc;
}

// fused pre+cell2: block = 2 d x 4 quadrants x 4 b; warp-per-weight-row
// grid (256, 8), 256 threads
__global__ void k_pre_cell2(const float* __restrict__ Ux, const float* __restrict__ Wx,
                            const float* __restrict__ bx, const float* __restrict__ ym_t,
                            float* __restrict__ hs_out, float* __restrict__ cs_out){
    __shared__ __align__(16) float hsh[4][512];
    __shared__ __align__(16) float ash[4][1024];
    __shared__ float gsm[4][2][4];
    int tid = threadIdx.x, lane = tid & 31, w = tid >> 5;
    int b0 = blockIdx.y*4;
    int d0 = blockIdx.x*2;
    for(int i=tid;i<4*512;i+=256){ int r=i>>9, k=i&511; hsh[r][k]=g_h1[(b0+r)*512+k]; }
    for(int i=tid;i<4*1024;i+=256){ int r=i>>10, k=i&1023; ash[r][k]=g_att[(b0+r)*CTXD+k]; }
    __syncthreads();
    int q = w >> 1, dd = w & 1;
    int j = q*512 + d0 + dd;
    const float4* u4=(const float4*)(Ux + (size_t)j*512);
    const float4* w4=(const float4*)(Wx + (size_t)j*1024);
    float acc[4];
    #pragma unroll
    for(int r=0;r<4;r++) acc[r]=0.f;
    #pragma unroll
    for(int it=0; it<4; it++){
        int k4 = it*32 + lane;
        float4 a = u4[k4];
        #pragma unroll
        for(int r=0;r<4;r++) acc[r] += dot4(a, *(const float4*)&hsh[r][k4*4]);
    }
    #pragma unroll
    for(int it=0; it<8; it++){
        int k4 = it*32 + lane;
        float4 c = w4[k4];
        #pragma unroll
        for(int r=0;r<4;r++) acc[r] += dot4(c, *(const float4*)&ash[r][k4*4]);
    }
    float bias = bx[j];
    #pragma unroll
    for(int r=0;r<4;r++){
        float s = warpSum(acc[r]);
        if(lane==0) gsm[q][dd][r] = s + bias;
    }
    __syncthreads();
    if(tid < 8){
        int r = tid & 3, d2 = tid >> 2;
        int b = b0 + r, d = d0 + d2;
        int i = b*512 + d;
        // order i,f,o,c
        float xi=gsm[0][d2][r], xf=gsm[1][d2][r], xo=gsm[2][d2][r], xc=gsm[3][d2][r];
        float c1=g_c1[i], h1=hsh[r][d], ym=ym_t[b];
        float c2 = sigf(xf)*c1 + sigf(xi)*tanhfast(xc);
        float h2 = sigf(xo)*tanhfast(c2);
        c2 = ym*c2 + (1.f-ym)*c1;
        h2 = ym*h2 + (1.f-ym)*h1;
        g_h[i]=h2; g_c[i]=c2;
        hs_out[i]=h2; cs_out[i]=c2;
    }
}

// ds[b,k]: warp-per-k, coalesced w_ds reads, 4-b tile; grid (64, 8)
__global__ void k_ds(const float* __restrict__ x_t, const float* __restrict__ w_ds,
                     const float* __restrict__ b_ds, const float* __restrict__ vvec,
                     const float* __restrict__ bv){
    __shared__ __align__(16) float hc[4][HCAT];
    int tid = threadIdx.x, lane = tid & 31, w = tid >> 5;
    int b0 = blockIdx.y*4;
    int k  = blockIdx.x*8 + w;
    for(int i=tid;i<4*512;i+=256){ int r=i>>9, kk=i&511; hc[r][kk]=g_h[(b0+r)*512+kk]; }
    for(int i=tid;i<4*1024;i+=256){ int r=i>>10, kk=i&1023; hc[r][512+kk]=g_att[(b0+r)*CTXD+kk]; }
    for(int i=tid;i<4*512;i+=256){ int r=i>>9, kk=i&511; hc[r][1536+kk]=x_t[(size_t)(b0+r)*512+kk]; }
    __syncthreads();
    const float4* w4=(const float4*)(w_ds + (size_t)k*HCAT);
    float acc[4];
    #pragma unroll
    for(int r=0;r<4;r++) acc[r]=0.f;
    #pragma unroll
    for(int it=0; it<16; it++){
        int k4 = it*32 + lane;
        float4 a = w4[k4];
        #pragma unroll
        for(int r=0;r<4;r++) acc[r] += dot4(a, *(const float4*)&hc[r][k4*4]);
    }
    float bias = b_ds[k];
    #pragma unroll
    for(int r=0;r<4;r++){
        float s = warpSum(acc[r]);
        if(lane==0) g_ds[(b0+r)*512 + k] = tanhfast(s + bias);
    }
    if(blockIdx.x==0 && w < 4){
        const float4* v4 = (const float4*)vvec;
        float pg = 0.f;
        #pragma unroll
        for(int it=0; it<16; it++){
            int k4 = it*32 + lane;
            pg += dot4(v4[k4], *(const float4*)&hc[w][k4*4]);
        }
        pg = warpSum(pg);
        if(lane==0) g_gg[b0+w] = sigf(pg + bv[0]);
    }
}

// logit[v,b] via packed FFMA2; 196 blocks, 2 v per thread; epilogue: softmax partials
__global__ void __launch_bounds__(128) k_logit(const float* __restrict__ w_logit,
                                               const float* __restrict__ b_logit){
    __shared__ __align__(16) unsigned long long dsp[128][16]; // 16 KB, ds packed b-pairs
    __shared__ float red[128*33];
    __shared__ float msave[32];
    int tid = threadIdx.x;
    int v0 = blockIdx.x*256 + tid;
    int v1 = v0 + 128;
    int v0c = v0 < VV ? v0 : VV-1;
    int v1c = v1 < VV ? v1 : VV-1;
    bool val0 = v0 < VV, val1 = v1 < VV;
    unsigned long long acc0[16], acc1[16];
    #pragma unroll
    for(int p=0;p<16;p++){ acc0[p]=0ULL; acc1[p]=0ULL; }
    for(int ch=0; ch<4; ch++){
        __syncthreads();
        for(int i=tid; i<2048; i+=128){
            int k = i >> 4, p = i & 15;
            int kk = ch*128 + k;
            dsp[k][p] = pack2(g_ds[(2*p)*512 + kk], g_ds[(2*p+1)*512 + kk]);
        }
        __syncthreads();
        const float4* w0=(const float4*)(w_logit + (size_t)v0c*512 + ch*128);
        const float4* w1=(const float4*)(w_logit + (size_t)v1c*512 + ch*128);
        #pragma unroll 1
        for(int k4=0;k4<32;k4++){
            float4 a=w0[k4], c=w1[k4];
            #pragma unroll
            for(int kc=0;kc<4;kc++){
                float av = (kc==0)?a.x:(kc==1)?a.y:(kc==2)?a.z:a.w;
                float cv = (kc==0)?c.x:(kc==1)?c.y:(kc==2)?c.z:c.w;
                unsigned long long a2 = dup2(av), c2 = dup2(cv);
                const ulonglong2* row = (const ulonglong2*)&dsp[k4*4+kc][0];
                #pragma unroll
                for(int qq=0;qq<8;qq++){
                    ulonglong2 pr = row[qq];
                    ffma2(acc0[2*qq],   a2, pr.x);
                    ffma2(acc0[2*qq+1], a2, pr.y);
                    ffma2(acc1[2*qq],   c2, pr.x);
                    ffma2(acc1[2*qq+1], c2, pr.y);
                }
            }
        }
    }
    float accf0[32], accf1[32];
    #pragma unroll
    for(int p=0;p<16;p++){
        unpack2(acc0[p], accf0[2*p], accf0[2*p+1]);
        unpack2(acc1[p], accf1[2*p], accf1[2*p+1]);
    }
    if(val0){
        float bl = b_logit[v0];
        #pragma unroll
        for(int b=0;b<32;b++) accf0[b]+=bl;
        float4* dst = (float4*)(g_logit + (size_t)v0*32);
        #pragma unroll
        for(int q=0;q<8;q++){
            float4 o; o.x=accf0[q*4]; o.y=accf0[q*4+1]; o.z=accf0[q*4+2]; o.w=accf0[q*4+3];
            dst[q]=o;
        }
    }
    if(val1){
        float bl = b_logit[v1];
        #pragma unroll
        for(int b=0;b<32;b++) accf1[b]+=bl;
        float4* dst = (float4*)(g_logit + (size_t)v1*32);
        #pragma unroll
        for(int q=0;q<8;q++){
            float4 o; o.x=accf1[q*4]; o.y=accf1[q*4+1]; o.z=accf1[q*4+2]; o.w=accf1[q*4+3];
            dst[q]=o;
        }
    }
    __syncthreads();
    #pragma unroll
    for(int b=0;b<32;b++){
        float m = -1e30f;
        if(val0) m = accf0[b];
        if(val1) m = fmaxf(m, accf1[b]);
        red[tid*33+b] = m;
    }
    __syncthreads();
    #pragma unroll
    for(int s=64;s>0;s>>=1){
        if(tid < s){
            #pragma unroll
            for(int b=0;b<32;b++)
                red[tid*33+b] = fmaxf(red[tid*33+b], red[(tid+s)*33+b]);
        }
        __syncthreads();
    }
    if(tid<32) msave[tid] = red[tid];
    __syncthreads();
    #pragma unroll
    for(int b=0;b<32;b++){
        float M = msave[b];
        float e = 0.f;
        if(val0) e += __expf(accf0[b]-M);
        if(val1) e += __expf(accf1[b]-M);
        red[tid*33+b] = e;
    }
    __syncthreads();
    #pragma unroll
    for(int s=64;s>0;s>>=1){
        if(tid < s){
            #pragma unroll
            for(int b=0;b<32;b++)
                red[tid*33+b] += red[(tid+s)*33+b];
        }
        __syncthreads();
    }
    if(tid<32){
        g_pm[blockIdx.x*32+tid] = msave[tid];
        g_ps[blockIdx.x*32+tid] = red[tid];
    }
}

// y_dec writer: final softmax reduce + scale + coalesced transpose
__global__ void k_sm3(float* __restrict__ yd){
    __shared__ float tile[32][33];
    __shared__ float sM[32], sI[32], sG[32];
    __shared__ float pm[8][32], ps[8][32];
    int tid = threadIdx.x;           // 256 threads
    int b = tid & 31, grp = tid >> 5;
    float M = -1e30f, S = 0.f;
    for(int ch=grp; ch<NCH; ch+=8){
        float m2 = g_pm[ch*32+b], s2 = g_ps[ch*32+b];
        float Mn = fmaxf(M, m2);
        S = S*__expf(M-Mn) + s2*__expf(m2-Mn);
        M = Mn;
    }
    pm[grp][b]=M; ps[grp][b]=S;
    __syncthreads();
    if(tid < 32){
        float Mf = pm[0][tid], Sf = ps[0][tid];
        #pragma unroll
        for(int k=1;k<8;k++){
            float m2=pm[k][tid], s2=ps[k][tid];
            float Mn=fmaxf(Mf,m2);
            Sf = Sf*__expf(Mf-Mn) + s2*__expf(m2-Mn);
            Mf = Mn;
        }
        sM[tid]=Mf; sI[tid]=1.f/Sf; sG[tid]=g_gg[tid];
    }
    __syncthreads();
    int vbase = blockIdx.x*256;
    for(int vt=0; vt<8; vt++){
        int v0t = vbase + vt*32;
        #pragma unroll
        for(int pass=0;pass<4;pass++){
            int vr = pass*8 + (tid>>5);
            int v  = v0t + vr;
            int bb = tid & 31;
            float val = 0.f;
            if(v < VV)
                val = sG[bb]*__expf(g_logit[(size_t)v*32+bb]-sM[bb])*sI[bb];
            tile[vr][bb] = val;
        }
        __syncthreads();
        #pragma unroll
        for(int pass=0;pass<4;pass++){
            int br = pass*8 + (tid>>5);
            int vl = tid & 31;
            int vw = v0t + vl;
            if(vw < VE) yd[(size_t)br*VE + vw] = tile[vl][br];
        }
        __syncthreads();
    }
}

// scatter-add (1-g)*watt at xid into y_dec
__global__ void k_scatter(const int* __restrict__ xid, float* __restrict__ yd){
    int i = blockIdx.x*256 + threadIdx.x;
    if(i >= BB*TXX) return;
    int tx = i >> 5, b = i & 31;
    int id = xid[tx*BB + b];
    if(id < 0 || id >= VE) return;
    float val = (1.f - g_gg[b]) * g_w[b*TXX + tx];
    atomicAdd(yd + (size_t)b*VE + id, val);
}

// ---------- host ----------
extern "C" void kernel_launch(void* const* d_in, const int* in_sizes, int n_in,
                              void* d_out, int out_size){
    const float* y_emb   = (const float*)d_in[0];
    const float* context = (const float*)d_in[1];
    const float* h0      = (const float*)d_in[2];
    const float* c0      = (const float*)d_in[3];
    const float* x_mask  = (const float*)d_in[4];
    const float* y_mask  = (const float*)d_in[5];
    const float* cov0    = (const float*)d_in[6];
    const float* Wih     = (const float*)d_in[7];
    const float* Whh     = (const float*)d_in[8];
    const float* bih     = (const float*)d_in[9];
    const float* bhh     = (const float*)d_in[10];
    const float* Wx      = (const float*)d_in[11];
    const float* Ux      = (const float*)d_in[12];
    const float* bx      = (const float*)d_in[13];
    const float* Wc      = (const float*)d_in[14];
    const float* b_att   = (const float*)d_in[15];
    const float* Wcomb   = (const float*)d_in[16];
    const float* Uatt    = (const float*)d_in[17];
    const float* Wcov    = (const float*)d_in[18];
    const float* w_ds    = (const float*)d_in[19];
    const float* b_ds    = (const float*)d_in[20];
    const float* w_logit = (const float*)d_in[21];
    const float* b_logit = (const float*)d_in[22];
    const float* vvec    = (const float*)d_in[23];
    const float* bv      = (const float*)d_in[24];
    const int*   xid     = (const int*)d_in[25];
    float* out = (float*)d_out;

    k_init<<<64,256>>>(h0, c0, cov0);
    k_pctx<<<dim3(TXX*BB/PCTB, CTXD/256), 256>>>(context, Wc, b_att);

    for(int t=0; t<TY; t++){
        const float* x_t = y_emb + (size_t)t*BB*DYD;
        const float* ym  = y_mask + (size_t)t*BB;

        k_gates_cell1<<<dim3(HH/2, BB/8), 256>>>(x_t, Wih, Whh, bih, bhh, ym,
                                                 out + OFF_SS + (long long)t*BB*2*HH);
        k_hq<<<dim3(CTXD/8, BB/8), 256>>>(Wcomb);
        k_scores<<<1600,256>>>(x_mask, Wcov, Uatt);
        k_smax_tx<<<BB,512>>>(x_mask,
                              out + OFF_DIS + (long long)t*BB*TXX,
                              out + OFF_COV + (long long)t*BB*TXX);
        k_atted<<<dim3(4,BB),256>>>(context, out + OFF_ATT + (long long)t*BB*CTXD);
        k_pre_cell2<<<dim3(HH/2, BB/4), 256>>>(Ux, Wx, bx, ym,
                                               out + OFF_HS  + (long long)t*BB*HH,
                                               out + OFF_CSo + (long long)t*BB*HH);
        k_ds<<<dim3(HH/8, BB/4), 256>>>(x_t, w_ds, b_ds, vvec, bv);
        k_logit<<<NCH,128>>>(w_logit, b_logit);
        k_sm3<<<NCH,256>>>(out + OFF_YD + (long long)t*BB*VE);
        k_scatter<<<50,256>>>(xid, out + OFF_YD + (long long)t*BB*VE);
    }
}

// round 17
// speedup vs baseline: 3.4253x; 1.2925x over previous
#include <cuda_runtime.h>
#include <cuda_bf16.h>
#include <math.h>

#define TY   50
#define BB   32
#define TXX  400
#define HH   512
#define CTXD 1024
#define DYD  512
#define G4   2048
#define VV   50000
#define VE   50050
#define HCAT 2048
#define NCHP 391      // k_logit blocks (391*128 = 50048) = softmax partial chunks
#define VPAD 50048

// Output layout: flattened tree leaves of ((hs,cs), ss, atts, dists, Cs, ydecs)
#define OFF_HS   0LL
#define OFF_CSo  819200LL
#define OFF_SS   1638400LL
#define OFF_ATT  3276800LL
#define OFF_DIS  4915200LL
#define OFF_COV  5555200LL
#define OFF_YD   6195200LL

// ---------- scratch ----------
__device__ float g_pctx[(size_t)TXX*BB*CTXD];   // 52.4 MB
__device__ float g_h[BB*HH], g_c[BB*HH];
__device__ float g_h1[BB*HH], g_c1[BB*HH];
__device__ float g_acc[BB*TXX];
__device__ float g_hq[BB*CTXD];
__device__ float g_sc[BB*TXX];
__device__ float g_w[BB*TXX];
__device__ float g_att[BB*CTXD];
__device__ __nv_bfloat16 g_dsb[BB*HH];          // ds in bf16
__device__ float g_gg[BB];
__device__ float g_logit[(size_t)VV*BB];        // [v][b], 6.4 MB
__device__ float g_pm[NCHP*BB], g_ps[NCHP*BB];
__device__ __nv_bfloat16 g_w16[(size_t)VPAD*512]; // w_logit bf16, 51.2 MB (pad rows zero-init)

// ---------- helpers ----------
__device__ __forceinline__ float sigf(float x){ return 1.f/(1.f+__expf(-x)); }
__device__ __forceinline__ float tanhfast(float x){
    x = fminf(15.f, fmaxf(-15.f, x));
    float e = __expf(2.f*x);
    return (e-1.f)/(e+1.f);
}
__device__ __forceinline__ float tanh_mufu(float x){
    float y;
    asm("tanh.approx.f32 %0, %1;" : "=f"(y) : "f"(x));
    return y;
}
__device__ __forceinline__ float warpSum(float v){
    #pragma unroll
    for(int o=16;o>0;o>>=1) v += __shfl_xor_sync(0xffffffffu, v, o);
    return v;
}
__device__ __forceinline__ float warpMax(float v){
    #pragma unroll
    for(int o=16;o>0;o>>=1) v = fmaxf(v, __shfl_xor_sync(0xffffffffu, v, o));
    return v;
}
__device__ __forceinline__ float dot4(float4 a, float4 b){
    return a.x*b.x + a.y*b.y + a.z*b.z + a.w*b.w;
}
__device__ __forceinline__ void mma_bf16(float &d0, float &d1, float &d2, float &d3,
                                         unsigned a0, unsigned a1, unsigned a2, unsigned a3,
                                         unsigned b0, unsigned b1){
    asm volatile("mma.sync.aligned.m16n8k16.row.col.f32.bf16.bf16.f32 "
                 "{%0,%1,%2,%3}, {%4,%5,%6,%7}, {%8,%9}, {%0,%1,%2,%3};"
                 : "+f"(d0), "+f"(d1), "+f"(d2), "+f"(d3)
                 : "r"(a0), "r"(a1), "r"(a2), "r"(a3), "r"(b0), "r"(b1));
}

// ---------- kernels ----------
__global__ void k_init(const float* __restrict__ h0, const float* __restrict__ c0,
                       const float* __restrict__ cov0){
    int i = blockIdx.x*256 + threadIdx.x;
    if(i < BB*HH){ g_h[i]=h0[i]; g_c[i]=c0[i]; }
    if(i < BB*TXX){ g_acc[i]=cov0[i]; }
}

// convert w_logit fp32 -> bf16 (8 elems/thread); grid 12500 x 256
__global__ void k_conv(const float* __restrict__ w){
    size_t i = ((size_t)blockIdx.x*256 + threadIdx.x)*8;
    if(i >= (size_t)VV*512) return;
    float4 x = *(const float4*)(w + i);
    float4 y = *(const float4*)(w + i + 4);
    __nv_bfloat162 t0 = __floats2bfloat162_rn(x.x, x.y);
    __nv_bfloat162 t1 = __floats2bfloat162_rn(x.z, x.w);
    __nv_bfloat162 t2 = __floats2bfloat162_rn(y.x, y.y);
    __nv_bfloat162 t3 = __floats2bfloat162_rn(y.z, y.w);
    uint4 o;
    o.x = *(unsigned*)&t0; o.y = *(unsigned*)&t1;
    o.z = *(unsigned*)&t2; o.w = *(unsigned*)&t3;
    *(uint4*)(g_w16 + i) = o;
}

// pctx[tb,d] = context[tb,:1024] . Wc[d,:1024] + b_att[d]
#define PCTB 8
__global__ void k_pctx(const float* __restrict__ ctx, const float* __restrict__ Wc,
                       const float* __restrict__ batt){
    __shared__ __align__(16) float xs[PCTB][CTXD];
    int tb0 = blockIdx.x*PCTB;
    int d   = blockIdx.y*256 + threadIdx.x;
    for(int i=threadIdx.x; i<PCTB*CTXD; i+=256){
        int r = i >> 10, k = i & 1023;
        xs[r][k] = ctx[(size_t)(tb0+r)*CTXD + k];
    }
    __syncthreads();
    const float4* w4 = (const float4*)(Wc + (size_t)d*CTXD);
    float acc[PCTB];
    #pragma unroll
    for(int r=0;r<PCTB;r++) acc[r]=0.f;
    #pragma unroll 2
    for(int k=0;k<CTXD/4;k++){
        float4 a = w4[k];
        #pragma unroll
        for(int r=0;r<PCTB;r++)
            acc[r] += dot4(a, *(const float4*)&xs[r][k*4]);
    }
    float bb = batt[d];
    #pragma unroll
    for(int r=0;r<PCTB;r++)
        g_pctx[(size_t)(tb0+r)*CTXD + d] = acc[r] + bb;
}

// fused gates+cell1 (unchanged from R16)
__global__ void k_gates_cell1(const float* __restrict__ x_t, const float* __restrict__ Wih,
                              const float* __restrict__ Whh, const float* __restrict__ bih,
                              const float* __restrict__ bhh, const float* __restrict__ ym_t,
                              float* __restrict__ ss_out){
    __shared__ __align__(16) float xs[8][DYD];
    __shared__ __align__(16) float hsm[8][HH];
    __shared__ float gsm[4][2][8];
    int tid = threadIdx.x, lane = tid & 31, w = tid >> 5;
    int b0 = blockIdx.y*8;
    int d0 = blockIdx.x*2;
    for(int i=tid;i<8*DYD;i+=256){ int r=i>>9, k=i&511; xs[r][k]=x_t[(size_t)(b0+r)*DYD+k]; }
    for(int i=tid;i<8*HH;i+=256){ int r=i>>9, k=i&511; hsm[r][k]=g_h[(b0+r)*HH+k]; }
    __syncthreads();
    int q = w >> 1, dd = w & 1;
    int j = q*512 + d0 + dd;
    const float4* wi=(const float4*)(Wih + (size_t)j*DYD);
    const float4* wh=(const float4*)(Whh + (size_t)j*HH);
    float acc[8];
    #pragma unroll
    for(int r=0;r<8;r++) acc[r]=0.f;
    #pragma unroll
    for(int it=0; it<4; it++){
        int k4 = it*32 + lane;
        float4 a = wi[k4];
        #pragma unroll
        for(int r=0;r<8;r++) acc[r] += dot4(a, *(const float4*)&xs[r][k4*4]);
        float4 c = wh[k4];
        #pragma unroll
        for(int r=0;r<8;r++) acc[r] += dot4(c, *(const float4*)&hsm[r][k4*4]);
    }
    float bias = bih[j] + bhh[j];
    #pragma unroll
    for(int r=0;r<8;r++){
        float s = warpSum(acc[r]);
        if(lane==0) gsm[q][dd][r] = s + bias;
    }
    __syncthreads();
    if(tid < 16){
        int r = tid & 7, d2 = tid >> 3;
        int b = b0 + r, d = d0 + d2;
        int i = b*512 + d;
        float gi=gsm[0][d2][r], gf=gsm[1][d2][r], gg=gsm[2][d2][r], go=gsm[3][d2][r];
        float cp=g_c[i], hp=hsm[r][d], ym=ym_t[b];
        float c1 = sigf(gf)*cp + sigf(gi)*tanhfast(gg);
        float h1 = sigf(go)*tanhfast(c1);
        h1 = ym*h1 + (1.f-ym)*hp;
        c1 = ym*c1 + (1.f-ym)*cp;
        g_h1[i]=h1; g_c1[i]=c1;
        ss_out[b*1024 + d]       = h1;
        ss_out[b*1024 + 512 + d] = c1;
    }
}

// hq[b,d]: warp-per-d, coalesced Wcomb reads, 8-b tile; grid (128, 4)
__global__ void k_hq(const float* __restrict__ Wcomb){
    __shared__ __align__(16) float s[8][1024];
    int tid = threadIdx.x, lane = tid & 31, w = tid >> 5;
    int b0 = blockIdx.y*8;
    int d  = blockIdx.x*8 + w;
    for(int i=tid;i<8*512;i+=256){ int r=i>>9, k=i&511; s[r][k]=g_h1[(b0+r)*512+k]; }
    for(int i=tid;i<8*512;i+=256){ int r=i>>9, k=i&511; s[r][512+k]=g_c1[(b0+r)*512+k]; }
    __syncthreads();
    const float4* w4=(const float4*)(Wcomb + (size_t)d*1024);
    float acc[8];
    #pragma unroll
    for(int r=0;r<8;r++) acc[r]=0.f;
    #pragma unroll
    for(int it=0; it<8; it++){
        int k4 = it*32 + lane;
        float4 a = w4[k4];
        #pragma unroll
        for(int r=0;r<8;r++) acc[r] += dot4(a, *(const float4*)&s[r][k4*4]);
    }
    #pragma unroll
    for(int r=0;r<8;r++){
        float v = warpSum(acc[r]);
        if(lane==0) g_hq[(b0+r)*1024 + d] = v;
    }
}

// scores[tx,b] (warp per (tx,b) pair)
__global__ void k_scores(const float* __restrict__ xmask, const float* __restrict__ wcov,
                         const float* __restrict__ uatt){
    int p    = blockIdx.x*8 + (threadIdx.x >> 5);
    int lane = threadIdx.x & 31;
    int b = p & 31, tx = p >> 5;
    float a = g_acc[b*TXX + tx];
    const float4* p4 = (const float4*)(g_pctx + (size_t)p*CTXD);
    const float4* h4 = (const float4*)(g_hq + (size_t)b*CTXD);
    const float4* w4 = (const float4*)wcov;
    const float4* u4 = (const float4*)uatt;
    float acc = 0.f;
    #pragma unroll
    for(int it=0; it<8; it++){
        int k = it*32 + lane;
        float4 pp=p4[k], hh=h4[k], ww=w4[k], uu=u4[k];
        acc += tanh_mufu(pp.x+hh.x+a*ww.x)*uu.x;
        acc += tanh_mufu(pp.y+hh.y+a*ww.y)*uu.y;
        acc += tanh_mufu(pp.z+hh.z+a*ww.z)*uu.z;
        acc += tanh_mufu(pp.w+hh.w+a*ww.w)*uu.w;
    }
    acc = warpSum(acc);
    if(lane==0) g_sc[b*TXX + tx] = acc * xmask[tx*BB + b];
}

// masked softmax over Tx per b; writes dists + Cs, updates coverage
__global__ void k_smax_tx(const float* __restrict__ xmask, float* __restrict__ dis_out,
                          float* __restrict__ cov_out){
    __shared__ float red[32];
    int b = blockIdx.x, tid = threadIdx.x;  // 512 threads
    float s = (tid < TXX) ? g_sc[b*TXX + tid] : -1e30f;
    float m = warpMax(s);
    if((tid&31)==0) red[tid>>5]=m;
    __syncthreads();
    if(tid<32){ float v=(tid<16)?red[tid]:-1e30f; v=warpMax(v); if(tid==0) red[0]=v; }
    __syncthreads();
    m = red[0];
    float xm = (tid < TXX) ? xmask[tid*BB + b] : 0.f;
    float e  = (tid < TXX) ? __expf(s - m)*xm : 0.f;
    __syncthreads();
    float ss = warpSum(e);
    if((tid&31)==0) red[tid>>5]=ss;
    __syncthreads();
    if(tid<32){ float v=(tid<16)?red[tid]:0.f; v=warpSum(v); if(tid==0) red[0]=v; }
    __syncthreads();
    float inv = 1.f/red[0];
    if(tid < TXX){
        float w = e*inv;
        g_w[b*TXX + tid] = w;
        dis_out[b*TXX + tid] = w;
        float aa = g_acc[b*TXX + tid];
        cov_out[b*TXX + tid] = aa;
        g_acc[b*TXX + tid] = aa + w;
    }
}

// atted[b,c] = sum_tx w[b,tx] * context[tx,b,c];  8-deep MLP unroll
__global__ void k_atted(const float* __restrict__ ctx, float* __restrict__ att_out){
    __shared__ float ws[TXX];
    int b = blockIdx.y;
    int c = blockIdx.x*256 + threadIdx.x;
    for(int k=threadIdx.x;k<TXX;k+=256) ws[k]=g_w[b*TXX+k];
    __syncthreads();
    const float* cb = ctx + (size_t)b*CTXD + c;
    const size_t str = (size_t)BB*CTXD;
    float a0=0.f,a1=0.f,a2=0.f,a3=0.f;
    #pragma unroll 2
    for(int t8=0;t8<TXX;t8+=8){
        float v0=cb[(t8+0)*str], v1=cb[(t8+1)*str], v2=cb[(t8+2)*str], v3=cb[(t8+3)*str];
        float v4=cb[(t8+4)*str], v5=cb[(t8+5)*str], v6=cb[(t8+6)*str], v7=cb[(t8+7)*str];
        a0 += ws[t8+0]*v0; a1 += ws[t8+1]*v1;
        a2 += ws[t8+2]*v2; a3 += ws[t8+3]*v3;
        a0 += ws[t8+4]*v4; a1 += ws[t8+5]*v5;
        a2 += ws[t8+6]*v6; a3 += ws[t8+7]*v7;
    }
    float acc = (a0+a1)+(a2+a3);
    g_att[b*CTXD+c]=acc;
    att_out[b*CTXD+c]=acc;
}

// fused pre+cell2 (unchanged from R16)
__global__ void k_pre_cell2(const float* __restrict__ Ux, const float* __restrict__ Wx,
                            const float* __restrict__ bx, const float* __restrict__ ym_t,
                            float* __restrict__ hs_out, float* __restrict__ cs_out){
    __shared__ __align__(16) float hsh[4][512];
    __shared__ __align__(16) float ash[4][1024];
    __shared__ float gsm[4][2][4];
    int tid = threadIdx.x, lane = tid & 31, w = tid >> 5;
    int b0 = blockIdx.y*4;
    int d0 = blockIdx.x*2;
    for(int i=tid;i<4*512;i+=256){ int r=i>>9, k=i&511; hsh[r][k]=g_h1[(b0+r)*512+k]; }
    for(int i=tid;i<4*1024;i+=256){ int r=i>>10, k=i&1023; ash[r][k]=g_att[(b0+r)*CTXD+k]; }
    __syncthreads();
    int q = w >> 1, dd = w & 1;
    int j = q*512 + d0 + dd;
    const float4* u4=(const float4*)(Ux + (size_t)j*512);
    const float4* w4=(const float4*)(Wx + (size_t)j*1024);
    float acc[4];
    #pragma unroll
    for(int r=0;r<4;r++) acc[r]=0.f;
    #pragma unroll
    for(int it=0; it<4; it++){
        int k4 = it*32 + lane;
        float4 a = u4[k4];
        #pragma unroll
        for(int r=0;r<4;r++) acc[r] += dot4(a, *(const float4*)&hsh[r][k4*4]);
    }
    #pragma unroll
    for(int it=0; it<8; it++){
        int k4 = it*32 + lane;
        float4 c = w4[k4];
        #pragma unroll
        for(int r=0;r<4;r++) acc[r] += dot4(c, *(const float4*)&ash[r][k4*4]);
    }
    float bias = bx[j];
    #pragma unroll
    for(int r=0;r<4;r++){
        float s = warpSum(acc[r]);
        if(lane==0) gsm[q][dd][r] = s + bias;
    }
    __syncthreads();
    if(tid < 8){
        int r = tid & 3, d2 = tid >> 2;
        int b = b0 + r, d = d0 + d2;
        int i = b*512 + d;
        float xi=gsm[0][d2][r], xf=gsm[1][d2][r], xo=gsm[2][d2][r], xc=gsm[3][d2][r];
        float c1=g_c1[i], h1=hsh[r][d], ym=ym_t[b];
        float c2 = sigf(xf)*c1 + sigf(xi)*tanhfast(xc);
        float h2 = sigf(xo)*tanhfast(c2);
        c2 = ym*c2 + (1.f-ym)*c1;
        h2 = ym*h2 + (1.f-ym)*h1;
        g_h[i]=h2; g_c[i]=c2;
        hs_out[i]=h2; cs_out[i]=c2;
    }
}

// ds[b,k] -> bf16; warp-per-k, 4-b tile; grid (64, 8)
__global__ void k_ds(const float* __restrict__ x_t, const float* __restrict__ w_ds,
                     const float* __restrict__ b_ds, const float* __restrict__ vvec,
                     const float* __restrict__ bv){
    __shared__ __align__(16) float hc[4][HCAT];
    int tid = threadIdx.x, lane = tid & 31, w = tid >> 5;
    int b0 = blockIdx.y*4;
    int k  = blockIdx.x*8 + w;
    for(int i=tid;i<4*512;i+=256){ int r=i>>9, kk=i&511; hc[r][kk]=g_h[(b0+r)*512+kk]; }
    for(int i=tid;i<4*1024;i+=256){ int r=i>>10, kk=i&1023; hc[r][512+kk]=g_att[(b0+r)*CTXD+kk]; }
    for(int i=tid;i<4*512;i+=256){ int r=i>>9, kk=i&511; hc[r][1536+kk]=x_t[(size_t)(b0+r)*512+kk]; }
    __syncthreads();
    const float4* w4=(const float4*)(w_ds + (size_t)k*HCAT);
    float acc[4];
    #pragma unroll
    for(int r=0;r<4;r++) acc[r]=0.f;
    #pragma unroll
    for(int it=0; it<16; it++){
        int k4 = it*32 + lane;
        float4 a = w4[k4];
        #pragma unroll
        for(int r=0;r<4;r++) acc[r] += dot4(a, *(const float4*)&hc[r][k4*4]);
    }
    float bias = b_ds[k];
    #pragma unroll
    for(int r=0;r<4;r++){
        float s = warpSum(acc[r]);
        if(lane==0) g_dsb[(b0+r)*512 + k] = __float2bfloat16(tanhfast(s + bias));
    }
    if(blockIdx.x==0 && w < 4){
        const float4* v4 = (const float4*)vvec;
        float pg = 0.f;
        #pragma unroll
        for(int it=0; it<16; it++){
            int k4 = it*32 + lane;
            pg += dot4(v4[k4], *(const float4*)&hc[w][k4*4]);
        }
        pg = warpSum(pg);
        if(lane==0) g_gg[b0+w] = sigf(pg + bv[0]);
    }
}

// logit[v,b] via bf16 tensor-core mma; block = v128 x b32, 8 warps
// epilogue: per-block softmax partials
__global__ void __launch_bounds__(256) k_logit(const float* __restrict__ b_logit){
    __shared__ __align__(16) unsigned char smb[18432 + 4224];
    __shared__ float red2[8*32];
    __shared__ float msave[32];
    __nv_bfloat16* As = (__nv_bfloat16*)smb;                 // [128][72]
    unsigned* B2 = (unsigned*)(smb + 18432);                 // [32][33] packed bf16 pairs
    int tid = threadIdx.x, lane = tid & 31, warp = tid >> 5;
    int v0g = blockIdx.x*128;
    int vw  = v0g + warp*16;
    float d[4][4];
    #pragma unroll
    for(int nt=0;nt<4;nt++){ d[nt][0]=0.f; d[nt][1]=0.f; d[nt][2]=0.f; d[nt][3]=0.f; }

    for(int kb=0; kb<512; kb+=64){
        __syncthreads();
        // stage A: 128 rows x 64 bf16 (row pad to 72)
        for(int i=tid; i<1024; i+=256){
            int r = i>>3, c = i&7;
            *(uint4*)(As + r*72 + c*8) =
                *(const uint4*)(g_w16 + (size_t)(v0g + r)*512 + kb + c*8);
        }
        // stage B: packed (k,k+1) bf16 pairs, [kp][b] with +1 pad
        for(int i=tid; i<1024; i+=256){
            int b = i>>5, kp = i&31;
            B2[kp*33 + b] = *(const unsigned*)(g_dsb + b*512 + kb + kp*2);
        }
        __syncthreads();
        #pragma unroll
        for(int kc=0; kc<4; kc++){
            unsigned a0,a1,a2,a3;
            int row = lane & 15, seg = lane >> 4;
            unsigned addr = (unsigned)__cvta_generic_to_shared(
                As + (warp*16 + row)*72 + kc*16 + seg*8);
            asm volatile("ldmatrix.sync.aligned.m8n8.x4.shared.b16 {%0,%1,%2,%3}, [%4];"
                         : "=r"(a0), "=r"(a1), "=r"(a2), "=r"(a3) : "r"(addr));
            int kp0 = kc*8 + (lane & 3);
            #pragma unroll
            for(int nt=0; nt<4; nt++){
                int bcol = nt*8 + (lane >> 2);
                unsigned b0 = B2[kp0*33 + bcol];
                unsigned b1 = B2[(kp0+4)*33 + bcol];
                mma_bf16(d[nt][0], d[nt][1], d[nt][2], d[nt][3], a0,a1,a2,a3, b0,b1);
            }
        }
    }
    // epilogue: bias + store logits + stage to smem for partials
    __syncthreads();
    float* ls = (float*)smb;   // [128][33] fp32, reuses A/B region
    {
        int row = lane >> 2, col = (lane & 3)*2;
        int vA = vw + row, vB = vw + row + 8;
        float blA = (vA < VV) ? b_logit[vA] : 0.f;
        float blB = (vB < VV) ? b_logit[vB] : 0.f;
        #pragma unroll
        for(int nt=0; nt<4; nt++){
            int b = nt*8 + col;
            float xA0 = d[nt][0] + blA, xA1 = d[nt][1] + blA;
            float xB0 = d[nt][2] + blB, xB1 = d[nt][3] + blB;
            if(vA < VV) *(float2*)(g_logit + (size_t)vA*32 + b) = make_float2(xA0, xA1);
            if(vB < VV) *(float2*)(g_logit + (size_t)vB*32 + b) = make_float2(xB0, xB1);
            int lA = warp*16 + row, lB = lA + 8;
            ls[lA*33 + b] = xA0;  ls[lA*33 + b + 1] = xA1;
            ls[lB*33 + b] = xB0;  ls[lB*33 + b + 1] = xB1;
        }
    }
    __syncthreads();
    // block softmax partials over the (valid) 128 v
    {
        int b = tid & 31, ch = tid >> 5;
        float m = -1e30f;
        #pragma unroll
        for(int q=0; q<16; q++){
            int vl = ch*16 + q;
            if(v0g + vl < VV) m = fmaxf(m, ls[vl*33 + b]);
        }
        red2[ch*32 + b] = m;
        __syncthreads();
        if(tid < 32){
            float M = red2[tid];
            #pragma unroll
            for(int c2=1;c2<8;c2++) M = fmaxf(M, red2[c2*32 + tid]);
            msave[tid] = M;
        }
        __syncthreads();
        float M = msave[b];
        float s = 0.f;
        #pragma unroll
        for(int q=0; q<16; q++){
            int vl = ch*16 + q;
            if(v0g + vl < VV) s += __expf(ls[vl*33 + b] - M);
        }
        red2[ch*32 + b] = s;
        __syncthreads();
        if(tid < 32){
            float S = red2[tid];
            #pragma unroll
            for(int c2=1;c2<8;c2++) S += red2[c2*32 + tid];
            g_pm[blockIdx.x*32 + tid] = msave[tid];
            g_ps[blockIdx.x*32 + tid] = S;
        }
    }
}

// y_dec writer: final softmax reduce over NCHP partials + scale + coalesced transpose
__global__ void k_sm3(float* __restrict__ yd){
    __shared__ float tile[32][33];
    __shared__ float sM[32], sI[32], sG[32];
    __shared__ float pm[8][32], ps[8][32];
    int tid = threadIdx.x;           // 256 threads
    int b = tid & 31, grp = tid >> 5;
    float M = -1e30f, S = 0.f;
    for(int ch=grp; ch<NCHP; ch+=8){
        float m2 = g_pm[ch*32+b], s2 = g_ps[ch*32+b];
        float Mn = fmaxf(M, m2);
        S = S*__expf(M-Mn) + s2*__expf(m2-Mn);
        M = Mn;
    }
    pm[grp][b]=M; ps[grp][b]=S;
    __syncthreads();
    if(tid < 32){
        float Mf = pm[0][tid], Sf = ps[0][tid];
        #pragma unroll
        for(int k=1;k<8;k++){
            float m2=pm[k][tid], s2=ps[k][tid];
            float Mn=fmaxf(Mf,m2);
            Sf = Sf*__expf(Mf-Mn) + s2*__expf(m2-Mn);
            Mf = Mn;
        }
        sM[tid]=Mf; sI[tid]=1.f/Sf; sG[tid]=g_gg[tid];
    }
    __syncthreads();
    int vbase = blockIdx.x*256;
    for(int vt=0; vt<8; vt++){
        int v0t = vbase + vt*32;
        #pragma unroll
        for(int pass=0;pass<4;pass++){
            int vr = pass*8 + (tid>>5);
            int v  = v0t + vr;
            int bb = tid & 31;
            float val = 0.f;
            if(v < VV)
                val = sG[bb]*__expf(g_logit[(size_t)v*32+bb]-sM[bb])*sI[bb];
            tile[vr][bb] = val;
        }
        __syncthreads();
        #pragma unroll
        for(int pass=0;pass<4;pass++){
            int br = pass*8 + (tid>>5);
            int vl = tid & 31;
            int vw = v0t + vl;
            if(vw < VE) yd[(size_t)br*VE + vw] = tile[vl][br];
        }
        __syncthreads();
    }
}

// scatter-add (1-g)*watt at xid into y_dec
__global__ void k_scatter(const int* __restrict__ xid, float* __restrict__ yd){
    int i = blockIdx.x*256 + threadIdx.x;
    if(i >= BB*TXX) return;
    int tx = i >> 5, b = i & 31;
    int id = xid[tx*BB + b];
    if(id < 0 || id >= VE) return;
    float val = (1.f - g_gg[b]) * g_w[b*TXX + tx];
    atomicAdd(yd + (size_t)b*VE + id, val);
}

// ---------- host ----------
extern "C" void kernel_launch(void* const* d_in, const int* in_sizes, int n_in,
                              void* d_out, int out_size){
    const float* y_emb   = (const float*)d_in[0];
    const float* context = (const float*)d_in[1];
    const float* h0      = (const float*)d_in[2];
    const float* c0      = (const float*)d_in[3];
    const float* x_mask  = (const float*)d_in[4];
    const float* y_mask  = (const float*)d_in[5];
    const float* cov0    = (const float*)d_in[6];
    const float* Wih     = (const float*)d_in[7];
    const float* Whh     = (const float*)d_in[8];
    const float* bih     = (const float*)d_in[9];
    const float* bhh     = (const float*)d_in[10];
    const float* Wx      = (const float*)d_in[11];
    const float* Ux      = (const float*)d_in[12];
    const float* bx      = (const float*)d_in[13];
    const float* Wc      = (const float*)d_in[14];
    const float* b_att   = (const float*)d_in[15];
    const float* Wcomb   = (const float*)d_in[16];
    const float* Uatt    = (const float*)d_in[17];
    const float* Wcov    = (const float*)d_in[18];
    const float* w_ds    = (const float*)d_in[19];
    const float* b_ds    = (const float*)d_in[20];
    const float* w_logit = (const float*)d_in[21];
    const float* b_logit = (const float*)d_in[22];
    const float* vvec    = (const float*)d_in[23];
    const float* bv      = (const float*)d_in[24];
    const int*   xid     = (const int*)d_in[25];
    float* out = (float*)d_out;

    k_init<<<64,256>>>(h0, c0, cov0);
    k_conv<<<12500,256>>>(w_logit);
    k_pctx<<<dim3(TXX*BB/PCTB, CTXD/256), 256>>>(context, Wc, b_att);

    for(int t=0; t<TY; t++){
        const float* x_t = y_emb + (size_t)t*BB*DYD;
        const float* ym  = y_mask + (size_t)t*BB;

        k_gates_cell1<<<dim3(HH/2, BB/8), 256>>>(x_t, Wih, Whh, bih, bhh, ym,
                                                 out + OFF_SS + (long long)t*BB*2*HH);
        k_hq<<<dim3(CTXD/8, BB/8), 256>>>(Wcomb);
        k_scores<<<1600,256>>>(x_mask, Wcov, Uatt);
        k_smax_tx<<<BB,512>>>(x_mask,
                              out + OFF_DIS + (long long)t*BB*TXX,
                              out + OFF_COV + (long long)t*BB*TXX);
        k_atted<<<dim3(4,BB),256>>>(context, out + OFF_ATT + (long long)t*BB*CTXD);
        k_pre_cell2<<<dim3(HH/2, BB/4), 256>>>(Ux, Wx, bx, ym,
                                               out + OFF_HS  + (long long)t*BB*HH,
                                               out + OFF_CSo + (long long)t*BB*HH);
        k_ds<<<dim3(HH/8, BB/4), 256>>>(x_t, w_ds, b_ds, vvec, bv);
        k_logit<<<NCHP,256>>>(b_logit);
        k_sm3<<<196,256>>>(out + OFF_YD + (long long)t*BB*VE);
        k_scatter<<<50,256>>>(xid, out + OFF_YD + (long long)t*BB*VE);
    }
}